// round 9
// baseline (speedup 1.0000x reference)
#include <cuda_runtime.h>
#include <cuda_fp16.h>
#include <cstdint>

#define NNODES 50000
#define NEDGES 850000
#define IN_DIM 256
#define HID 32
#define H1 8
#define OUT_DIM 64
#define HD1 (H1*HID)   // 256
#define KDIM 256

// ---------------- scratch ----------------
__device__ __align__(16) __half g_feat1h[NNODES * HD1];   // 25.6 MB fp16
__device__ __align__(16) float  g_h1[NNODES * HD1];       // 51.2 MB
__device__ __align__(16) __half g_feat2h[NNODES * OUT_DIM]; // 6.4 MB fp16
__device__ __align__(16) float  g_el1[NNODES * H1];
__device__ __align__(16) float  g_er1[NNODES * H1];
__device__ __align__(16) float  g_el2[NNODES];
__device__ __align__(16) float  g_er2[NNODES];
__device__ __align__(16) int    g_cnt[NNODES];
__device__ __align__(16) int    g_off[NNODES + 1];
__device__ __align__(16) int    g_cur[NNODES];
__device__ __align__(16) int    g_csr_src[NEDGES];

// packed f32x2 FMA: d.lo += a.lo*b.lo ; d.hi += a.hi*b.hi
#define FMA_X2(d, a, b) \
    asm("fma.rn.f32x2 %0, %1, %2, %0;" : "+l"(d) : "l"(a), "l"(b))

__device__ __forceinline__ uint32_t h2_bits(__half2 h) {
    uint32_t u;
    memcpy(&u, &h, 4);
    return u;
}

// ---------------- packed-fp32 GEMM, mov-free mainloop, fused attention epilogue ----------------
// Block: 128 rows x NT cols at colbase=blockIdx.y*NT. 256 threads: tr4=tid>>4, tc=tid&15.
// Thread: rows {8*tr4 .. +7} (4 row-pairs), cols {colbase+4tc+64q .. +3}.
// Smem: A k-major [32][ATSTR] (row-pairs adjacent); B duplicated (b,b) with bank swizzle.
// LAYER 1: C -> fp16 g_feat1h; el1/er1 per 32-col head.  LAYER 2: C -> fp16 g_feat2h; el2/er2 row.
#define ATSTR 132

template <int NT, int NCOL, int LAYER>
__global__ __launch_bounds__(256) void pgemm_kernel(
    const float* __restrict__ A, int M,
    const float* __restrict__ B,          // [KDIM][NCOL] row-major
    const float* __restrict__ al, const float* __restrict__ ar)
{
    constexpr int BDSTR = 2 * NT + NT / 4;     // dup row stride incl swizzle space
    constexpr int QN = NT / 64;
    constexpr int ABUFF = 32 * ATSTR;
    constexpr int BBUFF = 32 * BDSTR;
    constexpr int BLD = NT / 32;               // float4 B loads per thread
    extern __shared__ float smf[];
    float* At = smf;                            // [2][32][ATSTR]
    float* Bd = smf + 2 * ABUFF;                // [2][32][BDSTR]

    const int tid = threadIdx.x;
    const int lane = tid & 31;
    const int tc = tid & 15;
    const int tr4 = tid >> 4;
    const int blockRow = blockIdx.x * 128;
    const int colbase = blockIdx.y * NT;

    // A staging: thread loads row r=tid>>1, k-half kh, 16 floats
    const int ar_ = tid >> 1;
    const int kh = (tid & 1) * 16;
    const int agr = blockRow + ar_;
    const bool aval = agr < M;
    const float* aSrc = A + (size_t)agr * KDIM + kh;

    // B staging: thread loads k-row kb, cols cb..cb+NT/8-1
    const int kb = tid >> 3;
    const int cb = (tid & 7) * (NT / 8);
    const int jb = cb >> 4;
    const float* bSrc = B + (size_t)kb * NCOL + colbase + cb;
    float* bDstBase = Bd + kb * BDSTR + 2 * cb + 4 * jb;

    // compute-load offsets
    int boff[QN];
#pragma unroll
    for (int q = 0; q < QN; q++) {
        int c0 = 4 * tc + 64 * q;
        boff[q] = 2 * c0 + 4 * (c0 >> 4);
    }
    const int aoff = 8 * tr4;

    unsigned long long acc[4][QN][4];
#pragma unroll
    for (int p = 0; p < 4; p++)
#pragma unroll
        for (int q = 0; q < QN; q++)
#pragma unroll
            for (int m = 0; m < 4; m++) acc[p][q][m] = 0ull;

    float Ar[16];
    float Br[NT / 8];

    // ---- staging helpers (inlined) ----
    auto ldgA = [&](int c) {
#pragma unroll
        for (int j = 0; j < 4; j++) {
            float4 v = aval ? *(const float4*)(aSrc + c * 32 + j * 4)
                            : make_float4(0.f, 0.f, 0.f, 0.f);
            Ar[4 * j + 0] = v.x; Ar[4 * j + 1] = v.y; Ar[4 * j + 2] = v.z; Ar[4 * j + 3] = v.w;
        }
    };
    auto ldgB = [&](int c) {
#pragma unroll
        for (int j = 0; j < BLD; j++) {
            float4 v = *(const float4*)(bSrc + (size_t)c * 32 * NCOL + j * 4);
            Br[4 * j + 0] = v.x; Br[4 * j + 1] = v.y; Br[4 * j + 2] = v.z; Br[4 * j + 3] = v.w;
        }
    };
    auto stsAB = [&](int buf) {
        float* ad = At + buf * ABUFF;
#pragma unroll
        for (int j = 0; j < 16; j++) ad[(kh + j) * ATSTR + ar_] = Ar[j];
        float* bd = bDstBase + buf * BBUFF;
#pragma unroll
        for (int m = 0; m < NT / 16; m++) {
            float b0 = Br[2 * m], b1 = Br[2 * m + 1];
            *(float4*)(bd + 4 * m) = make_float4(b0, b0, b1, b1);
        }
    };

    // ---- prologue ----
    ldgA(0); ldgB(0);
    stsAB(0);
    ldgA(1); ldgB(1);
    __syncthreads();

    for (int c = 0; c < 8; c++) {
        const int buf = c & 1;
        const float* Ab = At + buf * ABUFF;
        const float* Bb = Bd + buf * BBUFF;
#pragma unroll 4
        for (int kk = 0; kk < 32; kk++) {
            unsigned long long ap[4];
            {
                float4 a0 = *(const float4*)&Ab[kk * ATSTR + aoff];
                float4 a1 = *(const float4*)&Ab[kk * ATSTR + aoff + 4];
                memcpy(&ap[0], &a0, 16);
                memcpy(&ap[2], &a1, 16);
            }
            unsigned long long bq[QN][4];
#pragma unroll
            for (int q = 0; q < QN; q++) {
                float4 b0 = *(const float4*)&Bb[kk * BDSTR + boff[q]];
                float4 b1 = *(const float4*)&Bb[kk * BDSTR + boff[q] + 4];
                memcpy(&bq[q][0], &b0, 16);
                memcpy(&bq[q][2], &b1, 16);
            }
#pragma unroll
            for (int p = 0; p < 4; p++)
#pragma unroll
                for (int q = 0; q < QN; q++)
#pragma unroll
                    for (int m = 0; m < 4; m++)
                        FMA_X2(acc[p][q][m], ap[p], bq[q][m]);
        }
        if (c < 7) {
            __syncthreads();
            stsAB(buf ^ 1);                       // chunk c+1
            if (c < 6) { ldgA(c + 2); ldgB(c + 2); }
            __syncthreads();
        }
    }

    // ---- epilogue: store fp16 C + fused el/er ----
#pragma unroll
    for (int p = 0; p < 4; p++) {
        const int r0 = blockRow + 8 * tr4 + 2 * p;
        const int r1 = r0 + 1;
        const bool v0 = r0 < M, v1 = r1 < M;
        float el0t = 0.f, er0t = 0.f, el1t = 0.f, er1t = 0.f;   // layer-2 whole-row sums
#pragma unroll
        for (int q = 0; q < QN; q++) {
            const int col = colbase + 4 * tc + 64 * q;
            float clo[4], chi[4];
#pragma unroll
            for (int m = 0; m < 4; m++) {
                uint2 u;
                memcpy(&u, &acc[p][q][m], 8);
                clo[m] = __uint_as_float(u.x);
                chi[m] = __uint_as_float(u.y);
            }
            float a0 = al[col], a1 = al[col + 1], a2 = al[col + 2], a3 = al[col + 3];
            float r0a = ar[col], r1a = ar[col + 1], r2a = ar[col + 2], r3a = ar[col + 3];
            float elL = clo[0] * a0 + clo[1] * a1 + clo[2] * a2 + clo[3] * a3;
            float erL = clo[0] * r0a + clo[1] * r1a + clo[2] * r2a + clo[3] * r3a;
            float elH = chi[0] * a0 + chi[1] * a1 + chi[2] * a2 + chi[3] * a3;
            float erH = chi[0] * r0a + chi[1] * r1a + chi[2] * r2a + chi[3] * r3a;

            // store fp16
            if (v0) {
                uint2 w = make_uint2(h2_bits(__floats2half2_rn(clo[0], clo[1])),
                                     h2_bits(__floats2half2_rn(clo[2], clo[3])));
                if (LAYER == 1) *(uint2*)&g_feat1h[(size_t)r0 * HD1 + col] = w;
                else            *(uint2*)&g_feat2h[(size_t)r0 * OUT_DIM + col] = w;
            }
            if (v1) {
                uint2 w = make_uint2(h2_bits(__floats2half2_rn(chi[0], chi[1])),
                                     h2_bits(__floats2half2_rn(chi[2], chi[3])));
                if (LAYER == 1) *(uint2*)&g_feat1h[(size_t)r1 * HD1 + col] = w;
                else            *(uint2*)&g_feat2h[(size_t)r1 * OUT_DIM + col] = w;
            }

            if (LAYER == 1) {
                // per-head reduce over 8-lane groups (cols span one 32-col head)
#pragma unroll
                for (int o = 1; o <= 4; o <<= 1) {
                    elL += __shfl_xor_sync(0xffffffffu, elL, o);
                    erL += __shfl_xor_sync(0xffffffffu, erL, o);
                    elH += __shfl_xor_sync(0xffffffffu, elH, o);
                    erH += __shfl_xor_sync(0xffffffffu, erH, o);
                }
                if ((lane & 7) == 0) {
                    int head = ((colbase + 64 * q) >> 5) + ((lane >> 3) & 1);
                    // lanes 0,16: tc group 0-7 -> head base; lanes 8,24: tc 8-15 -> head base+1
                    if (v0) { g_el1[r0 * H1 + head] = elL; g_er1[r0 * H1 + head] = erL; }
                    if (v1) { g_el1[r1 * H1 + head] = elH; g_er1[r1 * H1 + head] = erH; }
                }
            } else {
                el0t += elL; er0t += erL; el1t += elH; er1t += erH;
            }
        }
        if (LAYER == 2) {
#pragma unroll
            for (int o = 1; o <= 8; o <<= 1) {
                el0t += __shfl_xor_sync(0xffffffffu, el0t, o);
                er0t += __shfl_xor_sync(0xffffffffu, er0t, o);
                el1t += __shfl_xor_sync(0xffffffffu, el1t, o);
                er1t += __shfl_xor_sync(0xffffffffu, er1t, o);
            }
            if ((lane & 15) == 0) {
                if (v0) { g_el2[r0] = el0t; g_er2[r0] = er0t; }
                if (v1) { g_el2[r1] = el1t; g_er2[r1] = er1t; }
            }
        }
    }
}

// ---------------- CSR build ----------------
__global__ void zero_cnt_kernel() {
    int i = blockIdx.x * blockDim.x + threadIdx.x;
    if (i < NNODES) g_cnt[i] = 0;
}

__global__ void hist_kernel(const int* __restrict__ dst) {
    int e = blockIdx.x * blockDim.x + threadIdx.x;
    if (e < NEDGES) atomicAdd(&g_cnt[dst[e]], 1);
}

__global__ void scan_kernel() {
    __shared__ int warpsum[32];
    int tid = threadIdx.x, lane = tid & 31, wid = tid >> 5;
    int carry = 0;
    for (int base = 0; base < NNODES; base += 4096) {
        int idx = base + tid * 4;
        int v0 = 0, v1 = 0, v2 = 0, v3 = 0;
        if (idx + 3 < NNODES) {
            int4 t = *(const int4*)&g_cnt[idx];
            v0 = t.x; v1 = t.y; v2 = t.z; v3 = t.w;
        } else {
            if (idx + 0 < NNODES) v0 = g_cnt[idx + 0];
            if (idx + 1 < NNODES) v1 = g_cnt[idx + 1];
            if (idx + 2 < NNODES) v2 = g_cnt[idx + 2];
            if (idx + 3 < NNODES) v3 = g_cnt[idx + 3];
        }
        int tsum = v0 + v1 + v2 + v3;
        int x = tsum;
#pragma unroll
        for (int o = 1; o < 32; o <<= 1) {
            int t = __shfl_up_sync(0xffffffffu, x, o);
            if (lane >= o) x += t;
        }
        if (lane == 31) warpsum[wid] = x;
        __syncthreads();
        if (wid == 0) {
            int w = warpsum[lane];
#pragma unroll
            for (int o = 1; o < 32; o <<= 1) {
                int t = __shfl_up_sync(0xffffffffu, w, o);
                if (lane >= o) w += t;
            }
            warpsum[lane] = w;
        }
        __syncthreads();
        int wexcl = (wid == 0) ? 0 : warpsum[wid - 1];
        int total = warpsum[31];
        int p = carry + wexcl + x - tsum;
        if (idx + 0 < NNODES) { g_off[idx + 0] = p;                g_cur[idx + 0] = p; }
        if (idx + 1 < NNODES) { g_off[idx + 1] = p + v0;           g_cur[idx + 1] = p + v0; }
        if (idx + 2 < NNODES) { g_off[idx + 2] = p + v0 + v1;      g_cur[idx + 2] = p + v0 + v1; }
        if (idx + 3 < NNODES) { g_off[idx + 3] = p + v0 + v1 + v2; g_cur[idx + 3] = p + v0 + v1 + v2; }
        carry += total;
        __syncthreads();
    }
    if (tid == 0) g_off[NNODES] = carry;
}

__global__ void scatter_kernel(const int* __restrict__ src, const int* __restrict__ dst) {
    int e = blockIdx.x * blockDim.x + threadIdx.x;
    if (e < NEDGES) {
        int p = atomicAdd(&g_cur[dst[e]], 1);
        g_csr_src[p] = src[e];
    }
}

// ---------------- layer 1 aggregation: warp per dst node (fp16 feats) ----------------
__global__ void agg1_kernel(const float* __restrict__ b1) {
    int n = (blockIdx.x * blockDim.x + threadIdx.x) >> 5;
    if (n >= NNODES) return;
    int lane = threadIdx.x & 31;
    int hh = lane >> 2;
    int db = (lane & 3) * 8;     // 8 half elements

    float ern = g_er1[n * H1 + hh];
    float wsum = 0.f;
    float a[8];
#pragma unroll
    for (int k = 0; k < 8; k++) a[k] = 0.f;

    int beg = g_off[n], end = g_off[n + 1];
    for (int e = beg; e < end; e++) {
        int s = g_csr_src[e];
        float x = g_el1[s * H1 + hh] + ern;
        x = fmaxf(x, 0.2f * x);          // leaky_relu(0.2)
        float wgt = __expf(x);
        wsum += wgt;
        uint4 hv = *(const uint4*)(g_feat1h + (size_t)s * HD1 + hh * HID + db);
        const __half2* hp = (const __half2*)&hv;
        float2 f0 = __half22float2(hp[0]);
        float2 f1 = __half22float2(hp[1]);
        float2 f2 = __half22float2(hp[2]);
        float2 f3 = __half22float2(hp[3]);
        a[0] += wgt * f0.x; a[1] += wgt * f0.y;
        a[2] += wgt * f1.x; a[3] += wgt * f1.y;
        a[4] += wgt * f2.x; a[5] += wgt * f2.y;
        a[6] += wgt * f3.x; a[7] += wgt * f3.y;
    }

    float inv = 1.f / wsum;
    float* o = g_h1 + (size_t)n * HD1 + hh * HID + db;
    const float* bp = b1 + hh * HID + db;
#pragma unroll
    for (int k = 0; k < 8; k++) {
        float v = a[k] * inv + bp[k];
        a[k] = v > 0.f ? v : (__expf(v) - 1.f);   // ELU
    }
    *(float4*)o = make_float4(a[0], a[1], a[2], a[3]);
    *(float4*)(o + 4) = make_float4(a[4], a[5], a[6], a[7]);
}

// ---------------- layer 2 aggregation (fp16 feats) ----------------
__global__ void agg2_kernel(const float* __restrict__ b2, float* __restrict__ out) {
    int n = (blockIdx.x * blockDim.x + threadIdx.x) >> 5;
    if (n >= NNODES) return;
    int lane = threadIdx.x & 31;

    float ern = g_er2[n];
    float wsum = 0.f;
    float a0 = 0.f, a1 = 0.f;

    int beg = g_off[n], end = g_off[n + 1];
    for (int e = beg; e < end; e++) {
        int s = g_csr_src[e];
        float x = g_el2[s] + ern;
        x = fmaxf(x, 0.2f * x);
        float wgt = __expf(x);
        wsum += wgt;
        __half2 hv = *(const __half2*)(g_feat2h + (size_t)s * OUT_DIM + lane * 2);
        float2 f = __half22float2(hv);
        a0 += wgt * f.x;
        a1 += wgt * f.y;
    }

    float inv = 1.f / wsum;
    out[(size_t)n * OUT_DIM + lane * 2 + 0] = a0 * inv + b2[lane * 2 + 0];
    out[(size_t)n * OUT_DIM + lane * 2 + 1] = a1 * inv + b2[lane * 2 + 1];
}

// ---------------- launch ----------------
extern "C" void kernel_launch(void* const* d_in, const int* in_sizes, int n_in,
                              void* d_out, int out_size) {
    const float* h   = (const float*)d_in[0];
    const float* W1  = (const float*)d_in[1];
    const float* al1 = (const float*)d_in[2];
    const float* ar1 = (const float*)d_in[3];
    const float* b1  = (const float*)d_in[4];
    const float* W2  = (const float*)d_in[5];
    const float* al2 = (const float*)d_in[6];
    const float* ar2 = (const float*)d_in[7];
    const float* b2  = (const float*)d_in[8];
    const int*   src = (const int*)d_in[9];
    const int*   dst = (const int*)d_in[10];
    float* out = (float*)d_out;

    float* h1p;   cudaGetSymbolAddress((void**)&h1p, g_h1);

    const int SMEM1 = (2 * 32 * ATSTR + 2 * 32 * (2 * 128 + 32)) * 4;   // 107520
    const int SMEM2 = (2 * 32 * ATSTR + 2 * 32 * (2 * 64 + 16)) * 4;    // 70656
    static bool attr_done = false;
    if (!attr_done) {
        cudaFuncSetAttribute((const void*)pgemm_kernel<128, 256, 1>, cudaFuncAttributeMaxDynamicSharedMemorySize, SMEM1);
        cudaFuncSetAttribute((const void*)pgemm_kernel<64, 64, 2>,  cudaFuncAttributeMaxDynamicSharedMemorySize, SMEM2);
        attr_done = true;
    }

    static cudaStream_t s_csr = nullptr;
    static cudaEvent_t ev_fork = nullptr, ev_join = nullptr;
    if (s_csr == nullptr) {
        cudaStreamCreateWithFlags(&s_csr, cudaStreamNonBlocking);
        cudaEventCreateWithFlags(&ev_fork, cudaEventDisableTiming);
        cudaEventCreateWithFlags(&ev_join, cudaEventDisableTiming);
    }

    const int nwarpblocks = (NNODES * 32 + 255) / 256;
    const int eblocks = (NEDGES + 255) / 256;
    const int gblocks = (NNODES + 127) / 128;   // 391

    // fork: CSR build concurrent with GEMM1; gemm1 stays 4th submission for ncu window
    cudaEventRecord(ev_fork, 0);
    cudaStreamWaitEvent(s_csr, ev_fork, 0);
    zero_cnt_kernel<<<(NNODES + 255) / 256, 256, 0, s_csr>>>();          // 1
    hist_kernel<<<eblocks, 256, 0, s_csr>>>(dst);                        // 2
    scan_kernel<<<1, 1024, 0, s_csr>>>();                                // 3
    pgemm_kernel<128, 256, 1><<<dim3(gblocks, 2), 256, SMEM1>>>(h, NNODES, W1, al1, ar1);   // 4
    scatter_kernel<<<eblocks, 256, 0, s_csr>>>(src, dst);                // 5
    cudaEventRecord(ev_join, s_csr);

    cudaStreamWaitEvent(0, ev_join, 0);
    agg1_kernel<<<nwarpblocks, 256>>>(b1);                               // 6

    pgemm_kernel<64, 64, 2><<<dim3(gblocks, 1), 256, SMEM2>>>(h1p, NNODES, W2, al2, ar2);   // 7
    agg2_kernel<<<nwarpblocks, 256>>>(b2, out);                          // 8
}

// round 10
// speedup vs baseline: 1.7614x; 1.7614x over previous
#include <cuda_runtime.h>
#include <cuda_fp16.h>
#include <cstdint>

#define NNODES 50000
#define NEDGES 850000
#define IN_DIM 256
#define HID 32
#define H1 8
#define OUT_DIM 64
#define HD1 (H1*HID)   // 256
#define KDIM 256

// ---------------- scratch ----------------
__device__ __align__(16) __half g_hA[NNODES * KDIM];      // 25.6 MB fp16 copy of h
__device__ __align__(16) __half g_W1t[HD1 * KDIM];        // W1 transposed [N][K] fp16
__device__ __align__(16) __half g_feat1h[NNODES * HD1];   // 25.6 MB fp16
__device__ __align__(16) float  g_h1[NNODES * HD1];       // 51.2 MB
__device__ __align__(16) float  g_feat2[NNODES * OUT_DIM];
__device__ __align__(16) float  g_el1[NNODES * H1];
__device__ __align__(16) float  g_er1[NNODES * H1];
__device__ __align__(16) float  g_el2[NNODES];
__device__ __align__(16) float  g_er2[NNODES];
__device__ __align__(16) int    g_cnt[NNODES];
__device__ __align__(16) int    g_off[NNODES + 1];
__device__ __align__(16) int    g_cur[NNODES];
__device__ __align__(16) int    g_csr_src[NEDGES];

// packed f32x2 FMA (gemm2 only)
#define FMA_X2(d, a, b) \
    asm("fma.rn.f32x2 %0, %1, %2, %0;" : "+l"(d) : "l"(a), "l"(b))

// cp.async 16B with zfill (sz = 16 valid, 0 -> fill zeros)
#define CPA16(dst, src, sz) \
    asm volatile("cp.async.cg.shared.global [%0], [%1], 16, %2;" :: "r"(dst), "l"(src), "r"(sz) : "memory")
#define CP_COMMIT() asm volatile("cp.async.commit_group;" ::: "memory")
#define CP_WAIT1()  asm volatile("cp.async.wait_group 1;" ::: "memory")

__device__ __forceinline__ uint32_t smem_u32(const void* p) {
    uint32_t a;
    asm("{ .reg .u64 t; cvta.to.shared.u64 t, %1; cvt.u32.u64 %0, t; }" : "=r"(a) : "l"(p));
    return a;
}
__device__ __forceinline__ uint32_t h2_bits(__half2 h) {
    uint32_t u;
    memcpy(&u, &h, 4);
    return u;
}

__device__ __forceinline__ void mma_f16(float c[4], const uint32_t a[4], const uint32_t b[2]) {
    asm("mma.sync.aligned.m16n8k16.row.col.f32.f16.f16.f32 "
        "{%0,%1,%2,%3}, {%4,%5,%6,%7}, {%8,%9}, {%0,%1,%2,%3};"
        : "+f"(c[0]), "+f"(c[1]), "+f"(c[2]), "+f"(c[3])
        : "r"(a[0]), "r"(a[1]), "r"(a[2]), "r"(a[3]), "r"(b[0]), "r"(b[1]));
}

// ---------------- prep: h -> fp16, W1 -> transposed fp16 ----------------
#define HBLOCKS 12500   // NNODES*IN_DIM/(256*4)
__global__ void prep_kernel(const float* __restrict__ h, const float* __restrict__ W1) {
    int b = blockIdx.x;
    if (b < HBLOCKS) {
        int i = (b * 256 + threadIdx.x) * 4;
        float4 v = *(const float4*)(h + i);
        __half2 p0 = __floats2half2_rn(v.x, v.y);
        __half2 p1 = __floats2half2_rn(v.z, v.w);
        *(uint2*)&g_hA[i] = make_uint2(h2_bits(p0), h2_bits(p1));
    } else {
        int i = (b - HBLOCKS) * 256 + threadIdx.x;   // 0..65535
        int n = i >> 8, k = i & 255;
        g_W1t[i] = __float2half(W1[k * HD1 + n]);
    }
}

// ---------------- GEMM1: fp16 mma.sync m16n8k16, fp32 accum, fused el1/er1 ----------------
// Block 128 rows x 64 cols; 8 warps (4 m x 2 n); warp tile 32x32 (2 m16 x 4 n8).
// Smem: A [row][40 halves] (20 b32 stride), Bt [col][40 halves]; cp.async double-buffered, BK=32.
__global__ __launch_bounds__(256) void hgemm1_kernel(
    int M, const float* __restrict__ al, const float* __restrict__ ar)
{
    __shared__ __align__(16) __half Asm[2][128 * 40];
    __shared__ __align__(16) __half Bsm[2][64 * 40];

    const int tid = threadIdx.x;
    const int lane = tid & 31;
    const int warp = tid >> 5;
    const int g = lane >> 2;
    const int t = lane & 3;
    const int warpRow = (warp & 3) * 32;
    const int warpCol = (warp >> 2) * 32;
    const int blockRow = blockIdx.y * 128;
    const int colbase = blockIdx.x * 64;

    // staging maps
    const int arow = tid >> 1;
    const int aseg = (tid & 1) * 16;          // halves
    const int agr = blockRow + arow;
    const int asz = (agr < M) ? 16 : 0;
    const __half* aSrc = g_hA + (size_t)agr * KDIM + aseg;
    const int bcol = tid >> 2;
    const int bseg = (tid & 3) * 8;           // halves
    const __half* bSrc = g_W1t + (size_t)(colbase + bcol) * KDIM + bseg;
    const uint32_t aD0 = smem_u32(&Asm[0][arow * 40 + aseg]);
    const uint32_t aD1 = smem_u32(&Asm[1][arow * 40 + aseg]);
    const uint32_t bD0 = smem_u32(&Bsm[0][bcol * 40 + bseg]);
    const uint32_t bD1 = smem_u32(&Bsm[1][bcol * 40 + bseg]);

    float acc[2][4][4];
#pragma unroll
    for (int mi = 0; mi < 2; mi++)
#pragma unroll
        for (int ni = 0; ni < 4; ni++)
#pragma unroll
            for (int k = 0; k < 4; k++) acc[mi][ni][k] = 0.f;

    // prologue: chunk 0 -> buf 0
    CPA16(aD0, aSrc, asz);
    CPA16(aD0 + 16, aSrc + 8, asz);
    CPA16(bD0, bSrc, 16);
    CP_COMMIT();

    for (int c = 0; c < 8; c++) {
        const int buf = c & 1;
        if (c < 7) {
            const __half* as = aSrc + (c + 1) * 32;
            const __half* bs = bSrc + (c + 1) * 32;
            uint32_t ad = buf ? aD0 : aD1;
            uint32_t bd = buf ? bD0 : bD1;
            CPA16(ad, as, asz);
            CPA16(ad + 16, as + 8, asz);
            CPA16(bd, bs, 16);
        }
        CP_COMMIT();
        CP_WAIT1();
        __syncthreads();

        const uint32_t* A32 = (const uint32_t*)Asm[buf];
        const uint32_t* B32 = (const uint32_t*)Bsm[buf];
#pragma unroll
        for (int s = 0; s < 2; s++) {
            uint32_t afr[2][4];
#pragma unroll
            for (int mi = 0; mi < 2; mi++) {
                int r = warpRow + mi * 16 + g;
                int base = r * 20 + s * 8 + t;
                afr[mi][0] = A32[base];
                afr[mi][1] = A32[base + 8 * 20];
                afr[mi][2] = A32[base + 4];
                afr[mi][3] = A32[base + 8 * 20 + 4];
            }
            uint32_t bfr[4][2];
#pragma unroll
            for (int ni = 0; ni < 4; ni++) {
                int col = warpCol + ni * 8 + g;
                int bb = col * 20 + s * 8 + t;
                bfr[ni][0] = B32[bb];
                bfr[ni][1] = B32[bb + 4];
            }
#pragma unroll
            for (int mi = 0; mi < 2; mi++)
#pragma unroll
                for (int ni = 0; ni < 4; ni++)
                    mma_f16(acc[mi][ni], afr[mi], bfr[ni]);
        }
        __syncthreads();
    }

    // ---- epilogue: fp16 feat1 store + fused el1/er1 (head = warp's 32-col tile) ----
    const int head = (colbase + warpCol) >> 5;
#pragma unroll
    for (int mi = 0; mi < 2; mi++) {
        const int r0 = blockRow + warpRow + mi * 16 + g;
        const int r1 = r0 + 8;
        const bool v0 = r0 < M, v1 = r1 < M;
        float elA = 0.f, erA = 0.f, elB = 0.f, erB = 0.f;
#pragma unroll
        for (int ni = 0; ni < 4; ni++) {
            const int col = colbase + warpCol + ni * 8 + 2 * t;
            float c0 = acc[mi][ni][0], c1 = acc[mi][ni][1];
            float c2 = acc[mi][ni][2], c3 = acc[mi][ni][3];
            float a0 = al[col], a1 = al[col + 1];
            float q0 = ar[col], q1 = ar[col + 1];
            elA += c0 * a0 + c1 * a1;  erA += c0 * q0 + c1 * q1;
            elB += c2 * a0 + c3 * a1;  erB += c2 * q0 + c3 * q1;
            if (v0) *(uint32_t*)&g_feat1h[(size_t)r0 * HD1 + col] = h2_bits(__floats2half2_rn(c0, c1));
            if (v1) *(uint32_t*)&g_feat1h[(size_t)r1 * HD1 + col] = h2_bits(__floats2half2_rn(c2, c3));
        }
#pragma unroll
        for (int o = 1; o <= 2; o <<= 1) {
            elA += __shfl_xor_sync(0xffffffffu, elA, o);
            erA += __shfl_xor_sync(0xffffffffu, erA, o);
            elB += __shfl_xor_sync(0xffffffffu, elB, o);
            erB += __shfl_xor_sync(0xffffffffu, erB, o);
        }
        if (t == 0) {
            if (v0) { g_el1[r0 * H1 + head] = elA; g_er1[r0 * H1 + head] = erA; }
            if (v1) { g_el1[r1 * H1 + head] = elB; g_er1[r1 * H1 + head] = erB; }
        }
    }
}

// ---------------- GEMM2: packed-fp32 (R8 engine), fused el2/er2 ----------------
#define ASTR 36
template <int NT, int NCOL, int LAYER>
__global__ __launch_bounds__(256, 2) void pgemm_kernel(
    const float* __restrict__ A, int M,
    const float* __restrict__ B,
    float* __restrict__ Cout,
    const float* __restrict__ al, const float* __restrict__ ar)
{
    constexpr int BSTR = NT + 4;
    constexpr int QN = NT / 64;
    extern __shared__ float smf[];
    float* Asm = smf;
    float* Bsm = smf + 2 * 128 * ASTR;

    const int tid = threadIdx.x;
    const int lane = tid & 31;
    const int tc = tid & 15;
    const int tr = tid >> 4;
    const int blockRow = blockIdx.x * 128;
    const int colbase = blockIdx.y * NT;

    const int arow = tid >> 1;
    const int ak = (tid & 1) * 16;
    const int brow = tid >> 3;
    const int bcol = (tid & 7) * (NT / 8);

    unsigned long long acc[8][QN][2];
#pragma unroll
    for (int i = 0; i < 8; i++)
#pragma unroll
        for (int q = 0; q < QN; q++) { acc[i][q][0] = 0ull; acc[i][q][1] = 0ull; }

    const int agr = blockRow + arow;
    const int asz = (agr < M) ? 16 : 0;
    const float* aSrcBase = A + (size_t)agr * KDIM + ak;
    const float* bSrcBase = B + (size_t)brow * NCOL + colbase + bcol;
    uint32_t aDst0 = smem_u32(Asm + arow * ASTR + ak);
    uint32_t bDst0 = smem_u32(Bsm + brow * BSTR + bcol);
    constexpr uint32_t ABUF = 128 * ASTR * 4;
    constexpr uint32_t BBUF = 32 * BSTR * 4;

    {
#pragma unroll
        for (int j = 0; j < 4; j++) CPA16(aDst0 + j * 16, aSrcBase + j * 4, asz);
#pragma unroll
        for (int j = 0; j < NT / 32; j++) CPA16(bDst0 + j * 16, bSrcBase + j * 4, 16);
        CP_COMMIT();
    }

    for (int c = 0; c < KDIM / 32; c++) {
        const int buf = c & 1;
        if (c < KDIM / 32 - 1) {
            const float* aSrc = aSrcBase + (c + 1) * 32;
            const float* bSrc = bSrcBase + (size_t)(c + 1) * 32 * NCOL;
            uint32_t aD = aDst0 + (buf ^ 1) * ABUF;
            uint32_t bD = bDst0 + (buf ^ 1) * BBUF;
#pragma unroll
            for (int j = 0; j < 4; j++) CPA16(aD + j * 16, aSrc + j * 4, asz);
#pragma unroll
            for (int j = 0; j < NT / 32; j++) CPA16(bD + j * 16, bSrc + j * 4, 16);
        }
        CP_COMMIT();
        CP_WAIT1();
        __syncthreads();

        const float* Ab = Asm + buf * 128 * ASTR;
        const float* Bb = Bsm + buf * 32 * BSTR;
#pragma unroll 4
        for (int kk = 0; kk < 32; kk++) {
            unsigned long long a8[8], bq[QN][2];
#pragma unroll
            for (int i = 0; i < 8; i++) {
                float x = Ab[(tr + 16 * i) * ASTR + kk];
                asm("mov.b64 %0, {%1, %1};" : "=l"(a8[i]) : "f"(x));
            }
#pragma unroll
            for (int q = 0; q < QN; q++) {
                float4 bv = *(const float4*)&Bb[kk * BSTR + 4 * tc + 64 * q];
                memcpy(&bq[q][0], &bv.x, 8);
                memcpy(&bq[q][1], &bv.z, 8);
            }
#pragma unroll
            for (int i = 0; i < 8; i++)
#pragma unroll
                for (int q = 0; q < QN; q++) {
                    FMA_X2(acc[i][q][0], a8[i], bq[q][0]);
                    FMA_X2(acc[i][q][1], a8[i], bq[q][1]);
                }
        }
        __syncthreads();
    }

#pragma unroll
    for (int i = 0; i < 8; i++) {
        const int r = blockRow + tr + 16 * i;
        const bool v = r < M;
#pragma unroll
        for (int q = 0; q < QN; q++) {
            float c0, c1, c2, c3;
            memcpy(&c0, (char*)&acc[i][q][0] + 0, 4);
            memcpy(&c1, (char*)&acc[i][q][0] + 4, 4);
            memcpy(&c2, (char*)&acc[i][q][1] + 0, 4);
            memcpy(&c3, (char*)&acc[i][q][1] + 4, 4);
            const int col = colbase + 4 * tc + 64 * q;
            float el = c0 * al[col] + c1 * al[col + 1] + c2 * al[col + 2] + c3 * al[col + 3];
            float er = c0 * ar[col] + c1 * ar[col + 1] + c2 * ar[col + 2] + c3 * ar[col + 3];

            if (v) {
                float* crow = Cout + (size_t)r * OUT_DIM + col;
                *(float4*)crow = make_float4(c0, c1, c2, c3);
            }
#pragma unroll
            for (int o = 1; o <= 8; o <<= 1) {
                el += __shfl_xor_sync(0xffffffffu, el, o);
                er += __shfl_xor_sync(0xffffffffu, er, o);
            }
            if ((lane & 15) == 0 && v) {
                g_el2[r] = el;
                g_er2[r] = er;
            }
        }
    }
}

// ---------------- CSR build ----------------
__global__ void zero_cnt_kernel() {
    int i = blockIdx.x * blockDim.x + threadIdx.x;
    if (i < NNODES) g_cnt[i] = 0;
}

__global__ void hist_kernel(const int* __restrict__ dst) {
    int e = blockIdx.x * blockDim.x + threadIdx.x;
    if (e < NEDGES) atomicAdd(&g_cnt[dst[e]], 1);
}

__global__ void scan_kernel() {
    __shared__ int warpsum[32];
    int tid = threadIdx.x, lane = tid & 31, wid = tid >> 5;
    int carry = 0;
    for (int base = 0; base < NNODES; base += 4096) {
        int idx = base + tid * 4;
        int v0 = 0, v1 = 0, v2 = 0, v3 = 0;
        if (idx + 3 < NNODES) {
            int4 t = *(const int4*)&g_cnt[idx];
            v0 = t.x; v1 = t.y; v2 = t.z; v3 = t.w;
        } else {
            if (idx + 0 < NNODES) v0 = g_cnt[idx + 0];
            if (idx + 1 < NNODES) v1 = g_cnt[idx + 1];
            if (idx + 2 < NNODES) v2 = g_cnt[idx + 2];
            if (idx + 3 < NNODES) v3 = g_cnt[idx + 3];
        }
        int tsum = v0 + v1 + v2 + v3;
        int x = tsum;
#pragma unroll
        for (int o = 1; o < 32; o <<= 1) {
            int t = __shfl_up_sync(0xffffffffu, x, o);
            if (lane >= o) x += t;
        }
        if (lane == 31) warpsum[wid] = x;
        __syncthreads();
        if (wid == 0) {
            int w = warpsum[lane];
#pragma unroll
            for (int o = 1; o < 32; o <<= 1) {
                int t = __shfl_up_sync(0xffffffffu, w, o);
                if (lane >= o) w += t;
            }
            warpsum[lane] = w;
        }
        __syncthreads();
        int wexcl = (wid == 0) ? 0 : warpsum[wid - 1];
        int total = warpsum[31];
        int p = carry + wexcl + x - tsum;
        if (idx + 0 < NNODES) { g_off[idx + 0] = p;                g_cur[idx + 0] = p; }
        if (idx + 1 < NNODES) { g_off[idx + 1] = p + v0;           g_cur[idx + 1] = p + v0; }
        if (idx + 2 < NNODES) { g_off[idx + 2] = p + v0 + v1;      g_cur[idx + 2] = p + v0 + v1; }
        if (idx + 3 < NNODES) { g_off[idx + 3] = p + v0 + v1 + v2; g_cur[idx + 3] = p + v0 + v1 + v2; }
        carry += total;
        __syncthreads();
    }
    if (tid == 0) g_off[NNODES] = carry;
}

__global__ void scatter_kernel(const int* __restrict__ src, const int* __restrict__ dst) {
    int e = blockIdx.x * blockDim.x + threadIdx.x;
    if (e < NEDGES) {
        int p = atomicAdd(&g_cur[dst[e]], 1);
        g_csr_src[p] = src[e];
    }
}

// ---------------- layer 1 aggregation: warp per dst node (fp16 feats) ----------------
__global__ void agg1_kernel(const float* __restrict__ b1) {
    int n = (blockIdx.x * blockDim.x + threadIdx.x) >> 5;
    if (n >= NNODES) return;
    int lane = threadIdx.x & 31;
    int hh = lane >> 2;
    int db = (lane & 3) * 8;

    float ern = g_er1[n * H1 + hh];
    float wsum = 0.f;
    float a[8];
#pragma unroll
    for (int k = 0; k < 8; k++) a[k] = 0.f;

    int beg = g_off[n], end = g_off[n + 1];
    for (int e = beg; e < end; e++) {
        int s = g_csr_src[e];
        float x = g_el1[s * H1 + hh] + ern;
        x = fmaxf(x, 0.2f * x);
        float wgt = __expf(x);
        wsum += wgt;
        uint4 hv = *(const uint4*)(g_feat1h + (size_t)s * HD1 + hh * HID + db);
        const __half2* hp = (const __half2*)&hv;
        float2 f0 = __half22float2(hp[0]);
        float2 f1 = __half22float2(hp[1]);
        float2 f2 = __half22float2(hp[2]);
        float2 f3 = __half22float2(hp[3]);
        a[0] += wgt * f0.x; a[1] += wgt * f0.y;
        a[2] += wgt * f1.x; a[3] += wgt * f1.y;
        a[4] += wgt * f2.x; a[5] += wgt * f2.y;
        a[6] += wgt * f3.x; a[7] += wgt * f3.y;
    }

    float inv = 1.f / wsum;
    float* o = g_h1 + (size_t)n * HD1 + hh * HID + db;
    const float* bp = b1 + hh * HID + db;
#pragma unroll
    for (int k = 0; k < 8; k++) {
        float v = a[k] * inv + bp[k];
        a[k] = v > 0.f ? v : (__expf(v) - 1.f);
    }
    *(float4*)o = make_float4(a[0], a[1], a[2], a[3]);
    *(float4*)(o + 4) = make_float4(a[4], a[5], a[6], a[7]);
}

// ---------------- layer 2 aggregation ----------------
__global__ void agg2_kernel(const float* __restrict__ b2, float* __restrict__ out) {
    int n = (blockIdx.x * blockDim.x + threadIdx.x) >> 5;
    if (n >= NNODES) return;
    int lane = threadIdx.x & 31;

    float ern = g_er2[n];
    float wsum = 0.f;
    float a0 = 0.f, a1 = 0.f;

    int beg = g_off[n], end = g_off[n + 1];
    for (int e = beg; e < end; e++) {
        int s = g_csr_src[e];
        float x = g_el2[s] + ern;
        x = fmaxf(x, 0.2f * x);
        float wgt = __expf(x);
        wsum += wgt;
        float2 f = *(const float2*)(g_feat2 + (size_t)s * OUT_DIM + lane * 2);
        a0 += wgt * f.x;
        a1 += wgt * f.y;
    }

    float inv = 1.f / wsum;
    out[(size_t)n * OUT_DIM + lane * 2 + 0] = a0 * inv + b2[lane * 2 + 0];
    out[(size_t)n * OUT_DIM + lane * 2 + 1] = a1 * inv + b2[lane * 2 + 1];
}

// ---------------- launch ----------------
extern "C" void kernel_launch(void* const* d_in, const int* in_sizes, int n_in,
                              void* d_out, int out_size) {
    const float* h   = (const float*)d_in[0];
    const float* W1  = (const float*)d_in[1];
    const float* al1 = (const float*)d_in[2];
    const float* ar1 = (const float*)d_in[3];
    const float* b1  = (const float*)d_in[4];
    const float* W2  = (const float*)d_in[5];
    const float* al2 = (const float*)d_in[6];
    const float* ar2 = (const float*)d_in[7];
    const float* b2  = (const float*)d_in[8];
    const int*   src = (const int*)d_in[9];
    const int*   dst = (const int*)d_in[10];
    float* out = (float*)d_out;

    float* h1p;   cudaGetSymbolAddress((void**)&h1p, g_h1);
    float* feat2; cudaGetSymbolAddress((void**)&feat2, g_feat2);

    const int SMEM2 = 2 * 128 * ASTR * 4 + 2 * 32 * (64 + 4) * 4;    // 54272
    static bool attr_done = false;
    if (!attr_done) {
        cudaFuncSetAttribute((const void*)pgemm_kernel<64, 64, 2>, cudaFuncAttributeMaxDynamicSharedMemorySize, SMEM2);
        attr_done = true;
    }

    static cudaStream_t s_csr = nullptr;
    static cudaEvent_t ev_fork = nullptr, ev_join = nullptr;
    if (s_csr == nullptr) {
        cudaStreamCreateWithFlags(&s_csr, cudaStreamNonBlocking);
        cudaEventCreateWithFlags(&ev_fork, cudaEventDisableTiming);
        cudaEventCreateWithFlags(&ev_join, cudaEventDisableTiming);
    }

    const int nwarpblocks = (NNODES * 32 + 255) / 256;
    const int eblocks = (NEDGES + 255) / 256;
    const int gblocks = (NNODES + 127) / 128;   // 391

    // fork: CSR build concurrent with prep+GEMM1; hgemm1 is 4th submission (ncu window)
    cudaEventRecord(ev_fork, 0);
    cudaStreamWaitEvent(s_csr, ev_fork, 0);
    zero_cnt_kernel<<<(NNODES + 255) / 256, 256, 0, s_csr>>>();          // 1
    hist_kernel<<<eblocks, 256, 0, s_csr>>>(dst);                        // 2
    prep_kernel<<<HBLOCKS + 256, 256>>>(h, W1);                          // 3 (main)
    hgemm1_kernel<<<dim3(4, gblocks), 256>>>(NNODES, al1, ar1);          // 4 (main)
    scan_kernel<<<1, 1024, 0, s_csr>>>();                                // 5
    scatter_kernel<<<eblocks, 256, 0, s_csr>>>(src, dst);                // 6
    cudaEventRecord(ev_join, s_csr);

    cudaStreamWaitEvent(0, ev_join, 0);
    agg1_kernel<<<nwarpblocks, 256>>>(b1);                               // 7

    pgemm_kernel<64, 64, 2><<<dim3(gblocks, 1), 256, SMEM2>>>(h1p, NNODES, W2, feat2, al2, ar2);  // 8
    agg2_kernel<<<nwarpblocks, 256>>>(b2, out);                          // 9
}

// round 11
// speedup vs baseline: 2.1217x; 1.2046x over previous
#include <cuda_runtime.h>
#include <cuda_fp16.h>
#include <cstdint>

#define NNODES 50000
#define NEDGES 850000
#define IN_DIM 256
#define HID 32
#define H1 8
#define OUT_DIM 64
#define HD1 (H1*HID)   // 256
#define KDIM 256

// ---------------- scratch ----------------
__device__ __align__(16) __half g_hA[NNODES * KDIM];      // fp16 copy of h
__device__ __align__(16) __half g_W1t[HD1 * KDIM];        // W1^T [N][K] fp16
__device__ __align__(16) __half g_W2t[OUT_DIM * KDIM];    // W2^T [N][K] fp16
__device__ __align__(16) __half g_feat1h[NNODES * HD1];   // 25.6 MB
__device__ __align__(16) __half g_h1h[NNODES * HD1];      // 25.6 MB fp16 h1
__device__ __align__(16) __half g_feat2h[NNODES * OUT_DIM];
__device__ __align__(16) float  g_el1[NNODES * H1];
__device__ __align__(16) float  g_er1[NNODES * H1];
__device__ __align__(16) float  g_el2[NNODES];
__device__ __align__(16) float  g_er2[NNODES];
__device__ __align__(16) int    g_cnt[NNODES];
__device__ __align__(16) int    g_off[NNODES + 1];
__device__ __align__(16) int    g_cur[NNODES];
__device__ __align__(16) int    g_csr_src[NEDGES];

// cp.async 16B with zfill
#define CPA16(dst, src, sz) \
    asm volatile("cp.async.cg.shared.global [%0], [%1], 16, %2;" :: "r"(dst), "l"(src), "r"(sz) : "memory")
#define CP_COMMIT() asm volatile("cp.async.commit_group;" ::: "memory")
#define CP_WAIT1()  asm volatile("cp.async.wait_group 1;" ::: "memory")

__device__ __forceinline__ uint32_t smem_u32(const void* p) {
    uint32_t a;
    asm("{ .reg .u64 t; cvta.to.shared.u64 t, %1; cvt.u32.u64 %0, t; }" : "=r"(a) : "l"(p));
    return a;
}
__device__ __forceinline__ uint32_t h2_bits(__half2 h) {
    uint32_t u;
    memcpy(&u, &h, 4);
    return u;
}

__device__ __forceinline__ void mma_f16(float c[4], const uint32_t a[4], const uint32_t b[2]) {
    asm("mma.sync.aligned.m16n8k16.row.col.f32.f16.f16.f32 "
        "{%0,%1,%2,%3}, {%4,%5,%6,%7}, {%8,%9}, {%0,%1,%2,%3};"
        : "+f"(c[0]), "+f"(c[1]), "+f"(c[2]), "+f"(c[3])
        : "r"(a[0]), "r"(a[1]), "r"(a[2]), "r"(a[3]), "r"(b[0]), "r"(b[1]));
}

// ---------------- prep: h -> fp16, W1 -> W1^T fp16, W2 -> W2^T fp16 ----------------
#define HBLOCKS 12500   // NNODES*IN_DIM/(256*4)
__global__ void prep_kernel(const float* __restrict__ h, const float* __restrict__ W1,
                            const float* __restrict__ W2) {
    int b = blockIdx.x;
    if (b < HBLOCKS) {
        int i = (b * 256 + threadIdx.x) * 4;
        float4 v = *(const float4*)(h + i);
        __half2 p0 = __floats2half2_rn(v.x, v.y);
        __half2 p1 = __floats2half2_rn(v.z, v.w);
        *(uint2*)&g_hA[i] = make_uint2(h2_bits(p0), h2_bits(p1));
    } else if (b < HBLOCKS + 256) {
        int i = (b - HBLOCKS) * 256 + threadIdx.x;   // 0..65535
        int n = i >> 8, k = i & 255;
        g_W1t[i] = __float2half(W1[k * HD1 + n]);
    } else {
        int i = (b - HBLOCKS - 256) * 256 + threadIdx.x;   // 0..16383
        int n = i >> 8, k = i & 255;
        g_W2t[i] = __float2half(W2[k * OUT_DIM + n]);
    }
}

// ---------------- GEMM1: fp16 mma m16n8k16, fused el1/er1 ----------------
// Block 128 rows x 64 cols; 8 warps (4m x 2n); warp tile 32x32.
__global__ __launch_bounds__(256) void hgemm1_kernel(
    int M, const float* __restrict__ al, const float* __restrict__ ar)
{
    __shared__ __align__(16) __half Asm[2][128 * 40];
    __shared__ __align__(16) __half Bsm[2][64 * 40];

    const int tid = threadIdx.x;
    const int lane = tid & 31;
    const int warp = tid >> 5;
    const int g = lane >> 2;
    const int t = lane & 3;
    const int warpRow = (warp & 3) * 32;
    const int warpCol = (warp >> 2) * 32;
    const int blockRow = blockIdx.y * 128;
    const int colbase = blockIdx.x * 64;

    const int arow = tid >> 1;
    const int aseg = (tid & 1) * 16;
    const int agr = blockRow + arow;
    const int asz = (agr < M) ? 16 : 0;
    const __half* aSrc = g_hA + (size_t)agr * KDIM + aseg;
    const int bcol = tid >> 2;
    const int bseg = (tid & 3) * 8;
    const __half* bSrc = g_W1t + (size_t)(colbase + bcol) * KDIM + bseg;
    const uint32_t aD0 = smem_u32(&Asm[0][arow * 40 + aseg]);
    const uint32_t aD1 = smem_u32(&Asm[1][arow * 40 + aseg]);
    const uint32_t bD0 = smem_u32(&Bsm[0][bcol * 40 + bseg]);
    const uint32_t bD1 = smem_u32(&Bsm[1][bcol * 40 + bseg]);

    float acc[2][4][4];
#pragma unroll
    for (int mi = 0; mi < 2; mi++)
#pragma unroll
        for (int ni = 0; ni < 4; ni++)
#pragma unroll
            for (int k = 0; k < 4; k++) acc[mi][ni][k] = 0.f;

    CPA16(aD0, aSrc, asz);
    CPA16(aD0 + 16, aSrc + 8, asz);
    CPA16(bD0, bSrc, 16);
    CP_COMMIT();

    for (int c = 0; c < 8; c++) {
        const int buf = c & 1;
        if (c < 7) {
            const __half* as = aSrc + (c + 1) * 32;
            const __half* bs = bSrc + (c + 1) * 32;
            uint32_t ad = buf ? aD0 : aD1;
            uint32_t bd = buf ? bD0 : bD1;
            CPA16(ad, as, asz);
            CPA16(ad + 16, as + 8, asz);
            CPA16(bd, bs, 16);
        }
        CP_COMMIT();
        CP_WAIT1();
        __syncthreads();

        const uint32_t* A32 = (const uint32_t*)Asm[buf];
        const uint32_t* B32 = (const uint32_t*)Bsm[buf];
#pragma unroll
        for (int s = 0; s < 2; s++) {
            uint32_t afr[2][4];
#pragma unroll
            for (int mi = 0; mi < 2; mi++) {
                int r = warpRow + mi * 16 + g;
                int base = r * 20 + s * 8 + t;
                afr[mi][0] = A32[base];
                afr[mi][1] = A32[base + 8 * 20];
                afr[mi][2] = A32[base + 4];
                afr[mi][3] = A32[base + 8 * 20 + 4];
            }
            uint32_t bfr[4][2];
#pragma unroll
            for (int ni = 0; ni < 4; ni++) {
                int col = warpCol + ni * 8 + g;
                int bb = col * 20 + s * 8 + t;
                bfr[ni][0] = B32[bb];
                bfr[ni][1] = B32[bb + 4];
            }
#pragma unroll
            for (int mi = 0; mi < 2; mi++)
#pragma unroll
                for (int ni = 0; ni < 4; ni++)
                    mma_f16(acc[mi][ni], afr[mi], bfr[ni]);
        }
        __syncthreads();
    }

    const int head = (colbase + warpCol) >> 5;
#pragma unroll
    for (int mi = 0; mi < 2; mi++) {
        const int r0 = blockRow + warpRow + mi * 16 + g;
        const int r1 = r0 + 8;
        const bool v0 = r0 < M, v1 = r1 < M;
        float elA = 0.f, erA = 0.f, elB = 0.f, erB = 0.f;
#pragma unroll
        for (int ni = 0; ni < 4; ni++) {
            const int col = colbase + warpCol + ni * 8 + 2 * t;
            float c0 = acc[mi][ni][0], c1 = acc[mi][ni][1];
            float c2 = acc[mi][ni][2], c3 = acc[mi][ni][3];
            float a0 = al[col], a1 = al[col + 1];
            float q0 = ar[col], q1 = ar[col + 1];
            elA += c0 * a0 + c1 * a1;  erA += c0 * q0 + c1 * q1;
            elB += c2 * a0 + c3 * a1;  erB += c2 * q0 + c3 * q1;
            if (v0) *(uint32_t*)&g_feat1h[(size_t)r0 * HD1 + col] = h2_bits(__floats2half2_rn(c0, c1));
            if (v1) *(uint32_t*)&g_feat1h[(size_t)r1 * HD1 + col] = h2_bits(__floats2half2_rn(c2, c3));
        }
#pragma unroll
        for (int o = 1; o <= 2; o <<= 1) {
            elA += __shfl_xor_sync(0xffffffffu, elA, o);
            erA += __shfl_xor_sync(0xffffffffu, erA, o);
            elB += __shfl_xor_sync(0xffffffffu, elB, o);
            erB += __shfl_xor_sync(0xffffffffu, erB, o);
        }
        if (t == 0) {
            if (v0) { g_el1[r0 * H1 + head] = elA; g_er1[r0 * H1 + head] = erA; }
            if (v1) { g_el1[r1 * H1 + head] = elB; g_er1[r1 * H1 + head] = erB; }
        }
    }
}

// ---------------- GEMM2: fp16 mma, 4 warps, warp tile 32x64, fused el2/er2 ----------------
__global__ __launch_bounds__(128) void hgemm2_kernel(
    int M, const float* __restrict__ al, const float* __restrict__ ar)
{
    __shared__ __align__(16) __half Asm[2][128 * 40];
    __shared__ __align__(16) __half Bsm[2][64 * 40];

    const int tid = threadIdx.x;
    const int lane = tid & 31;
    const int warp = tid >> 5;          // 0..3
    const int g = lane >> 2;
    const int t = lane & 3;
    const int warpRow = warp * 32;
    const int blockRow = blockIdx.x * 128;

    // staging: A 128 rows x 32 halves (4 CPA16/thread); B 64 cols x 32 halves (2 CPA16/thread)
    const int arow = tid;               // 0..127
    const int agr = blockRow + arow;
    const int asz = (agr < M) ? 16 : 0;
    const __half* aSrc = g_h1h + (size_t)agr * KDIM;
    const int bcol = tid >> 1;
    const int bseg = (tid & 1) * 16;
    const __half* bSrc = g_W2t + (size_t)bcol * KDIM + bseg;
    const uint32_t aD0 = smem_u32(&Asm[0][arow * 40]);
    const uint32_t aD1 = smem_u32(&Asm[1][arow * 40]);
    const uint32_t bD0 = smem_u32(&Bsm[0][bcol * 40 + bseg]);
    const uint32_t bD1 = smem_u32(&Bsm[1][bcol * 40 + bseg]);

    float acc[2][8][4];
#pragma unroll
    for (int mi = 0; mi < 2; mi++)
#pragma unroll
        for (int ni = 0; ni < 8; ni++)
#pragma unroll
            for (int k = 0; k < 4; k++) acc[mi][ni][k] = 0.f;

#pragma unroll
    for (int j = 0; j < 4; j++) CPA16(aD0 + j * 16, aSrc + j * 8, asz);
    CPA16(bD0, bSrc, 16);
    CPA16(bD0 + 16, bSrc + 8, 16);
    CP_COMMIT();

    for (int c = 0; c < 8; c++) {
        const int buf = c & 1;
        if (c < 7) {
            const __half* as = aSrc + (c + 1) * 32;
            const __half* bs = bSrc + (c + 1) * 32;
            uint32_t ad = buf ? aD0 : aD1;
            uint32_t bd = buf ? bD0 : bD1;
#pragma unroll
            for (int j = 0; j < 4; j++) CPA16(ad + j * 16, as + j * 8, asz);
            CPA16(bd, bs, 16);
            CPA16(bd + 16, bs + 8, 16);
        }
        CP_COMMIT();
        CP_WAIT1();
        __syncthreads();

        const uint32_t* A32 = (const uint32_t*)Asm[buf];
        const uint32_t* B32 = (const uint32_t*)Bsm[buf];
#pragma unroll
        for (int s = 0; s < 2; s++) {
            uint32_t afr[2][4];
#pragma unroll
            for (int mi = 0; mi < 2; mi++) {
                int r = warpRow + mi * 16 + g;
                int base = r * 20 + s * 8 + t;
                afr[mi][0] = A32[base];
                afr[mi][1] = A32[base + 8 * 20];
                afr[mi][2] = A32[base + 4];
                afr[mi][3] = A32[base + 8 * 20 + 4];
            }
            uint32_t bfr[8][2];
#pragma unroll
            for (int ni = 0; ni < 8; ni++) {
                int col = ni * 8 + g;
                int bb = col * 20 + s * 8 + t;
                bfr[ni][0] = B32[bb];
                bfr[ni][1] = B32[bb + 4];
            }
#pragma unroll
            for (int mi = 0; mi < 2; mi++)
#pragma unroll
                for (int ni = 0; ni < 8; ni++)
                    mma_f16(acc[mi][ni], afr[mi], bfr[ni]);
        }
        __syncthreads();
    }

#pragma unroll
    for (int mi = 0; mi < 2; mi++) {
        const int r0 = blockRow + warpRow + mi * 16 + g;
        const int r1 = r0 + 8;
        const bool v0 = r0 < M, v1 = r1 < M;
        float elA = 0.f, erA = 0.f, elB = 0.f, erB = 0.f;
#pragma unroll
        for (int ni = 0; ni < 8; ni++) {
            const int col = ni * 8 + 2 * t;
            float c0 = acc[mi][ni][0], c1 = acc[mi][ni][1];
            float c2 = acc[mi][ni][2], c3 = acc[mi][ni][3];
            float a0 = al[col], a1 = al[col + 1];
            float q0 = ar[col], q1 = ar[col + 1];
            elA += c0 * a0 + c1 * a1;  erA += c0 * q0 + c1 * q1;
            elB += c2 * a0 + c3 * a1;  erB += c2 * q0 + c3 * q1;
            if (v0) *(uint32_t*)&g_feat2h[(size_t)r0 * OUT_DIM + col] = h2_bits(__floats2half2_rn(c0, c1));
            if (v1) *(uint32_t*)&g_feat2h[(size_t)r1 * OUT_DIM + col] = h2_bits(__floats2half2_rn(c2, c3));
        }
#pragma unroll
        for (int o = 1; o <= 2; o <<= 1) {
            elA += __shfl_xor_sync(0xffffffffu, elA, o);
            erA += __shfl_xor_sync(0xffffffffu, erA, o);
            elB += __shfl_xor_sync(0xffffffffu, elB, o);
            erB += __shfl_xor_sync(0xffffffffu, erB, o);
        }
        if (t == 0) {
            if (v0) { g_el2[r0] = elA; g_er2[r0] = erA; }
            if (v1) { g_el2[r1] = elB; g_er2[r1] = erB; }
        }
    }
}

// ---------------- CSR build ----------------
__global__ void zero_cnt_kernel() {
    int i = blockIdx.x * blockDim.x + threadIdx.x;
    if (i < NNODES) g_cnt[i] = 0;
}

__global__ void hist_kernel(const int* __restrict__ dst) {
    int e = blockIdx.x * blockDim.x + threadIdx.x;
    if (e < NEDGES) atomicAdd(&g_cnt[dst[e]], 1);
}

__global__ void scan_kernel() {
    __shared__ int warpsum[32];
    int tid = threadIdx.x, lane = tid & 31, wid = tid >> 5;
    int carry = 0;
    for (int base = 0; base < NNODES; base += 4096) {
        int idx = base + tid * 4;
        int v0 = 0, v1 = 0, v2 = 0, v3 = 0;
        if (idx + 3 < NNODES) {
            int4 t = *(const int4*)&g_cnt[idx];
            v0 = t.x; v1 = t.y; v2 = t.z; v3 = t.w;
        } else {
            if (idx + 0 < NNODES) v0 = g_cnt[idx + 0];
            if (idx + 1 < NNODES) v1 = g_cnt[idx + 1];
            if (idx + 2 < NNODES) v2 = g_cnt[idx + 2];
            if (idx + 3 < NNODES) v3 = g_cnt[idx + 3];
        }
        int tsum = v0 + v1 + v2 + v3;
        int x = tsum;
#pragma unroll
        for (int o = 1; o < 32; o <<= 1) {
            int t = __shfl_up_sync(0xffffffffu, x, o);
            if (lane >= o) x += t;
        }
        if (lane == 31) warpsum[wid] = x;
        __syncthreads();
        if (wid == 0) {
            int w = warpsum[lane];
#pragma unroll
            for (int o = 1; o < 32; o <<= 1) {
                int t = __shfl_up_sync(0xffffffffu, w, o);
                if (lane >= o) w += t;
            }
            warpsum[lane] = w;
        }
        __syncthreads();
        int wexcl = (wid == 0) ? 0 : warpsum[wid - 1];
        int total = warpsum[31];
        int p = carry + wexcl + x - tsum;
        if (idx + 0 < NNODES) { g_off[idx + 0] = p;                g_cur[idx + 0] = p; }
        if (idx + 1 < NNODES) { g_off[idx + 1] = p + v0;           g_cur[idx + 1] = p + v0; }
        if (idx + 2 < NNODES) { g_off[idx + 2] = p + v0 + v1;      g_cur[idx + 2] = p + v0 + v1; }
        if (idx + 3 < NNODES) { g_off[idx + 3] = p + v0 + v1 + v2; g_cur[idx + 3] = p + v0 + v1 + v2; }
        carry += total;
        __syncthreads();
    }
    if (tid == 0) g_off[NNODES] = carry;
}

__global__ void scatter_kernel(const int* __restrict__ src, const int* __restrict__ dst) {
    int e = blockIdx.x * blockDim.x + threadIdx.x;
    if (e < NEDGES) {
        int p = atomicAdd(&g_cur[dst[e]], 1);
        g_csr_src[p] = src[e];
    }
}

// ---------------- layer 1 aggregation: warp per dst node; writes fp16 h1 ----------------
__global__ void agg1_kernel(const float* __restrict__ b1) {
    int n = (blockIdx.x * blockDim.x + threadIdx.x) >> 5;
    if (n >= NNODES) return;
    int lane = threadIdx.x & 31;
    int hh = lane >> 2;
    int db = (lane & 3) * 8;

    float ern = g_er1[n * H1 + hh];
    float wsum = 0.f;
    float a[8];
#pragma unroll
    for (int k = 0; k < 8; k++) a[k] = 0.f;

    int beg = g_off[n], end = g_off[n + 1];
    for (int e = beg; e < end; e++) {
        int s = g_csr_src[e];
        float x = g_el1[s * H1 + hh] + ern;
        x = fmaxf(x, 0.2f * x);
        float wgt = __expf(x);
        wsum += wgt;
        uint4 hv = *(const uint4*)(g_feat1h + (size_t)s * HD1 + hh * HID + db);
        const __half2* hp = (const __half2*)&hv;
        float2 f0 = __half22float2(hp[0]);
        float2 f1 = __half22float2(hp[1]);
        float2 f2 = __half22float2(hp[2]);
        float2 f3 = __half22float2(hp[3]);
        a[0] += wgt * f0.x; a[1] += wgt * f0.y;
        a[2] += wgt * f1.x; a[3] += wgt * f1.y;
        a[4] += wgt * f2.x; a[5] += wgt * f2.y;
        a[6] += wgt * f3.x; a[7] += wgt * f3.y;
    }

    float inv = 1.f / wsum;
    const float* bp = b1 + hh * HID + db;
#pragma unroll
    for (int k = 0; k < 8; k++) {
        float v = a[k] * inv + bp[k];
        a[k] = v > 0.f ? v : (__expf(v) - 1.f);   // ELU
    }
    uint4 w = make_uint4(h2_bits(__floats2half2_rn(a[0], a[1])),
                         h2_bits(__floats2half2_rn(a[2], a[3])),
                         h2_bits(__floats2half2_rn(a[4], a[5])),
                         h2_bits(__floats2half2_rn(a[6], a[7])));
    *(uint4*)&g_h1h[(size_t)n * HD1 + hh * HID + db] = w;
}

// ---------------- layer 2 aggregation (fp16 feats) ----------------
__global__ void agg2_kernel(const float* __restrict__ b2, float* __restrict__ out) {
    int n = (blockIdx.x * blockDim.x + threadIdx.x) >> 5;
    if (n >= NNODES) return;
    int lane = threadIdx.x & 31;

    float ern = g_er2[n];
    float wsum = 0.f;
    float a0 = 0.f, a1 = 0.f;

    int beg = g_off[n], end = g_off[n + 1];
    for (int e = beg; e < end; e++) {
        int s = g_csr_src[e];
        float x = g_el2[s] + ern;
        x = fmaxf(x, 0.2f * x);
        float wgt = __expf(x);
        wsum += wgt;
        __half2 hv = *(const __half2*)(g_feat2h + (size_t)s * OUT_DIM + lane * 2);
        float2 f = __half22float2(hv);
        a0 += wgt * f.x;
        a1 += wgt * f.y;
    }

    float inv = 1.f / wsum;
    out[(size_t)n * OUT_DIM + lane * 2 + 0] = a0 * inv + b2[lane * 2 + 0];
    out[(size_t)n * OUT_DIM + lane * 2 + 1] = a1 * inv + b2[lane * 2 + 1];
}

// ---------------- launch ----------------
extern "C" void kernel_launch(void* const* d_in, const int* in_sizes, int n_in,
                              void* d_out, int out_size) {
    const float* h   = (const float*)d_in[0];
    const float* W1  = (const float*)d_in[1];
    const float* al1 = (const float*)d_in[2];
    const float* ar1 = (const float*)d_in[3];
    const float* b1  = (const float*)d_in[4];
    const float* W2  = (const float*)d_in[5];
    const float* al2 = (const float*)d_in[6];
    const float* ar2 = (const float*)d_in[7];
    const float* b2  = (const float*)d_in[8];
    const int*   src = (const int*)d_in[9];
    const int*   dst = (const int*)d_in[10];
    float* out = (float*)d_out;

    static cudaStream_t s_csr = nullptr;
    static cudaEvent_t ev_fork = nullptr, ev_join = nullptr;
    if (s_csr == nullptr) {
        cudaStreamCreateWithFlags(&s_csr, cudaStreamNonBlocking);
        cudaEventCreateWithFlags(&ev_fork, cudaEventDisableTiming);
        cudaEventCreateWithFlags(&ev_join, cudaEventDisableTiming);
    }

    const int nwarpblocks = (NNODES * 32 + 255) / 256;
    const int eblocks = (NEDGES + 255) / 256;
    const int gblocks = (NNODES + 127) / 128;   // 391

    // fork: CSR build concurrent with prep+GEMM1; hgemm1 stays 4th submission (ncu window)
    cudaEventRecord(ev_fork, 0);
    cudaStreamWaitEvent(s_csr, ev_fork, 0);
    zero_cnt_kernel<<<(NNODES + 255) / 256, 256, 0, s_csr>>>();          // 1
    hist_kernel<<<eblocks, 256, 0, s_csr>>>(dst);                        // 2
    prep_kernel<<<HBLOCKS + 256 + 64, 256>>>(h, W1, W2);                 // 3 (main)
    hgemm1_kernel<<<dim3(4, gblocks), 256>>>(NNODES, al1, ar1);          // 4 (main)
    scan_kernel<<<1, 1024, 0, s_csr>>>();                                // 5
    scatter_kernel<<<eblocks, 256, 0, s_csr>>>(src, dst);                // 6
    cudaEventRecord(ev_join, s_csr);

    cudaStreamWaitEvent(0, ev_join, 0);
    agg1_kernel<<<nwarpblocks, 256>>>(b1);                               // 7
    hgemm2_kernel<<<gblocks, 128>>>(NNODES, al2, ar2);                   // 8
    agg2_kernel<<<nwarpblocks, 256>>>(b2, out);                          // 9
}

// round 12
// speedup vs baseline: 2.1489x; 1.0128x over previous
#include <cuda_runtime.h>
#include <cuda_fp16.h>
#include <cstdint>

#define NNODES 50000
#define NEDGES 850000
#define IN_DIM 256
#define HID 32
#define H1 8
#define OUT_DIM 64
#define HD1 (H1*HID)   // 256
#define KDIM 256

// ---------------- scratch ----------------
__device__ __align__(16) __half g_hA[NNODES * KDIM];
__device__ __align__(16) __half g_W1t[HD1 * KDIM];
__device__ __align__(16) __half g_W2t[OUT_DIM * KDIM];
__device__ __align__(16) __half g_feat1h[NNODES * HD1];
__device__ __align__(16) __half g_h1h[NNODES * HD1];
__device__ __align__(16) __half g_feat2h[NNODES * OUT_DIM];
__device__ __align__(16) float  g_el1[NNODES * H1];
__device__ __align__(16) float  g_er1[NNODES * H1];
__device__ __align__(16) float  g_el2[NNODES];
__device__ __align__(16) float  g_er2[NNODES];
__device__ __align__(16) int    g_cnt[NNODES];
__device__ __align__(16) int    g_off[NNODES + 1];
__device__ __align__(16) int    g_cur[NNODES];
__device__ __align__(16) int    g_csr_src[NEDGES];

#define CPA16(dst, src, sz) \
    asm volatile("cp.async.cg.shared.global [%0], [%1], 16, %2;" :: "r"(dst), "l"(src), "r"(sz) : "memory")
#define CP_COMMIT() asm volatile("cp.async.commit_group;" ::: "memory")
#define CP_WAIT1()  asm volatile("cp.async.wait_group 1;" ::: "memory")

#define LDSM_X4(r0, r1, r2, r3, addr) \
    asm volatile("ldmatrix.sync.aligned.m8n8.x4.shared.b16 {%0,%1,%2,%3}, [%4];" \
        : "=r"(r0), "=r"(r1), "=r"(r2), "=r"(r3) : "r"(addr))

__device__ __forceinline__ uint32_t smem_u32(const void* p) {
    uint32_t a;
    asm("{ .reg .u64 t; cvta.to.shared.u64 t, %1; cvt.u32.u64 %0, t; }" : "=r"(a) : "l"(p));
    return a;
}
__device__ __forceinline__ uint32_t h2_bits(__half2 h) {
    uint32_t u;
    memcpy(&u, &h, 4);
    return u;
}

__device__ __forceinline__ void mma_f16(float c[4], const uint32_t a[4], const uint32_t b[2]) {
    asm("mma.sync.aligned.m16n8k16.row.col.f32.f16.f16.f32 "
        "{%0,%1,%2,%3}, {%4,%5,%6,%7}, {%8,%9}, {%0,%1,%2,%3};"
        : "+f"(c[0]), "+f"(c[1]), "+f"(c[2]), "+f"(c[3])
        : "r"(a[0]), "r"(a[1]), "r"(a[2]), "r"(a[3]), "r"(b[0]), "r"(b[1]));
}

// ---------------- prep ----------------
#define HBLOCKS 12500
__global__ void prep_kernel(const float* __restrict__ h, const float* __restrict__ W1,
                            const float* __restrict__ W2) {
    int b = blockIdx.x;
    if (b < HBLOCKS) {
        int i = (b * 256 + threadIdx.x) * 4;
        float4 v = *(const float4*)(h + i);
        __half2 p0 = __floats2half2_rn(v.x, v.y);
        __half2 p1 = __floats2half2_rn(v.z, v.w);
        *(uint2*)&g_hA[i] = make_uint2(h2_bits(p0), h2_bits(p1));
    } else if (b < HBLOCKS + 256) {
        int i = (b - HBLOCKS) * 256 + threadIdx.x;
        int n = i >> 8, k = i & 255;
        g_W1t[i] = __float2half(W1[k * HD1 + n]);
    } else {
        int i = (b - HBLOCKS - 256) * 256 + threadIdx.x;
        int n = i >> 8, k = i & 255;
        g_W2t[i] = __float2half(W2[k * OUT_DIM + n]);
    }
}

// ---------------- GEMM1: fp16 mma + ldmatrix, fused el1/er1 ----------------
// Block 128x64; 8 warps (4m x 2n); warp tile 32x32. Smem row stride 40 halves (80B).
__global__ __launch_bounds__(256) void hgemm1_kernel(
    int M, const float* __restrict__ al, const float* __restrict__ ar)
{
    __shared__ __align__(16) __half Asm[2][128 * 40];   // 10240 B per buf
    __shared__ __align__(16) __half Bsm[2][64 * 40];    // 5120 B per buf

    const int tid = threadIdx.x;
    const int lane = tid & 31;
    const int warp = tid >> 5;
    const int g = lane >> 2;
    const int t = lane & 3;
    const int warpRow = (warp & 3) * 32;
    const int warpCol = (warp >> 2) * 32;
    const int blockRow = blockIdx.y * 128;
    const int colbase = blockIdx.x * 64;

    const int arow = tid >> 1;
    const int aseg = (tid & 1) * 16;
    const int agr = blockRow + arow;
    const int asz = (agr < M) ? 16 : 0;
    const __half* aSrc = g_hA + (size_t)agr * KDIM + aseg;
    const int bcol = tid >> 2;
    const int bseg = (tid & 3) * 8;
    const __half* bSrc = g_W1t + (size_t)(colbase + bcol) * KDIM + bseg;
    const uint32_t aD0 = smem_u32(&Asm[0][arow * 40 + aseg]);
    const uint32_t aD1 = smem_u32(&Asm[1][arow * 40 + aseg]);
    const uint32_t bD0 = smem_u32(&Bsm[0][bcol * 40 + bseg]);
    const uint32_t bD1 = smem_u32(&Bsm[1][bcol * 40 + bseg]);

    // ldmatrix lane addresses (bytes): A rows for x4 (m0: rows0-7 k0-7, m1: rows8-15, m2: rows0-7 k+8, m3: rows8-15 k+8)
    const uint32_t aL0 = smem_u32(&Asm[0][0]) + (warpRow + (lane & 15)) * 80 + (lane >> 4) * 16;
    // B pairs: m0: cols p*16+0..7 k0-7, m1: same cols k+8, m2: cols +8 k0-7, m3: cols +8 k+8
    const uint32_t bL0 = smem_u32(&Bsm[0][0]) + (warpCol + (lane & 7) + ((lane >> 4) << 3)) * 80 + (((lane >> 3) & 1) * 16);

    float acc[2][4][4];
#pragma unroll
    for (int mi = 0; mi < 2; mi++)
#pragma unroll
        for (int ni = 0; ni < 4; ni++)
#pragma unroll
            for (int k = 0; k < 4; k++) acc[mi][ni][k] = 0.f;

    CPA16(aD0, aSrc, asz);
    CPA16(aD0 + 16, aSrc + 8, asz);
    CPA16(bD0, bSrc, 16);
    CP_COMMIT();

    for (int c = 0; c < 8; c++) {
        const int buf = c & 1;
        if (c < 7) {
            const __half* as = aSrc + (c + 1) * 32;
            const __half* bs = bSrc + (c + 1) * 32;
            uint32_t ad = buf ? aD0 : aD1;
            uint32_t bd = buf ? bD0 : bD1;
            CPA16(ad, as, asz);
            CPA16(ad + 16, as + 8, asz);
            CPA16(bd, bs, 16);
        }
        CP_COMMIT();
        CP_WAIT1();
        __syncthreads();

        const uint32_t aB = aL0 + buf * 10240;
        const uint32_t bB = bL0 + buf * 5120;
#pragma unroll
        for (int s = 0; s < 2; s++) {
            uint32_t afr[2][4], bfr[4][2];
#pragma unroll
            for (int mi = 0; mi < 2; mi++)
                LDSM_X4(afr[mi][0], afr[mi][1], afr[mi][2], afr[mi][3],
                        aB + mi * (16 * 80) + s * 32);
#pragma unroll
            for (int p = 0; p < 2; p++)
                LDSM_X4(bfr[2 * p][0], bfr[2 * p][1], bfr[2 * p + 1][0], bfr[2 * p + 1][1],
                        bB + p * (16 * 80) + s * 32);
            // afr order from ldmatrix: {m0=rowsLo kLo, m1=rowsHi kLo, m2=rowsLo kHi, m3=rowsHi kHi}
            // matches mma a-frag {a0,a1,a2,a3} (verified equal to scalar indexing pattern)
#pragma unroll
            for (int mi = 0; mi < 2; mi++)
#pragma unroll
                for (int ni = 0; ni < 4; ni++)
                    mma_f16(acc[mi][ni], afr[mi], bfr[ni]);
        }
        __syncthreads();
    }

    const int head = (colbase + warpCol) >> 5;
#pragma unroll
    for (int mi = 0; mi < 2; mi++) {
        const int r0 = blockRow + warpRow + mi * 16 + g;
        const int r1 = r0 + 8;
        const bool v0 = r0 < M, v1 = r1 < M;
        float elA = 0.f, erA = 0.f, elB = 0.f, erB = 0.f;
#pragma unroll
        for (int ni = 0; ni < 4; ni++) {
            const int col = colbase + warpCol + ni * 8 + 2 * t;
            float c0 = acc[mi][ni][0], c1 = acc[mi][ni][1];
            float c2 = acc[mi][ni][2], c3 = acc[mi][ni][3];
            float a0 = al[col], a1 = al[col + 1];
            float q0 = ar[col], q1 = ar[col + 1];
            elA += c0 * a0 + c1 * a1;  erA += c0 * q0 + c1 * q1;
            elB += c2 * a0 + c3 * a1;  erB += c2 * q0 + c3 * q1;
            if (v0) *(uint32_t*)&g_feat1h[(size_t)r0 * HD1 + col] = h2_bits(__floats2half2_rn(c0, c1));
            if (v1) *(uint32_t*)&g_feat1h[(size_t)r1 * HD1 + col] = h2_bits(__floats2half2_rn(c2, c3));
        }
#pragma unroll
        for (int o = 1; o <= 2; o <<= 1) {
            elA += __shfl_xor_sync(0xffffffffu, elA, o);
            erA += __shfl_xor_sync(0xffffffffu, erA, o);
            elB += __shfl_xor_sync(0xffffffffu, elB, o);
            erB += __shfl_xor_sync(0xffffffffu, erB, o);
        }
        if (t == 0) {
            if (v0) { g_el1[r0 * H1 + head] = elA; g_er1[r0 * H1 + head] = erA; }
            if (v1) { g_el1[r1 * H1 + head] = elB; g_er1[r1 * H1 + head] = erB; }
        }
    }
}

// ---------------- GEMM2: fp16 mma + ldmatrix, 4 warps, warp tile 32x64 ----------------
__global__ __launch_bounds__(128) void hgemm2_kernel(
    int M, const float* __restrict__ al, const float* __restrict__ ar)
{
    __shared__ __align__(16) __half Asm[2][128 * 40];
    __shared__ __align__(16) __half Bsm[2][64 * 40];

    const int tid = threadIdx.x;
    const int lane = tid & 31;
    const int warp = tid >> 5;
    const int g = lane >> 2;
    const int t = lane & 3;
    const int warpRow = warp * 32;
    const int blockRow = blockIdx.x * 128;

    const int arow = tid;
    const int agr = blockRow + arow;
    const int asz = (agr < M) ? 16 : 0;
    const __half* aSrc = g_h1h + (size_t)agr * KDIM;
    const int bcol = tid >> 1;
    const int bseg = (tid & 1) * 16;
    const __half* bSrc = g_W2t + (size_t)bcol * KDIM + bseg;
    const uint32_t aD0 = smem_u32(&Asm[0][arow * 40]);
    const uint32_t aD1 = smem_u32(&Asm[1][arow * 40]);
    const uint32_t bD0 = smem_u32(&Bsm[0][bcol * 40 + bseg]);
    const uint32_t bD1 = smem_u32(&Bsm[1][bcol * 40 + bseg]);

    const uint32_t aL0 = smem_u32(&Asm[0][0]) + (warpRow + (lane & 15)) * 80 + (lane >> 4) * 16;
    const uint32_t bL0 = smem_u32(&Bsm[0][0]) + ((lane & 7) + ((lane >> 4) << 3)) * 80 + (((lane >> 3) & 1) * 16);

    float acc[2][8][4];
#pragma unroll
    for (int mi = 0; mi < 2; mi++)
#pragma unroll
        for (int ni = 0; ni < 8; ni++)
#pragma unroll
            for (int k = 0; k < 4; k++) acc[mi][ni][k] = 0.f;

#pragma unroll
    for (int j = 0; j < 4; j++) CPA16(aD0 + j * 16, aSrc + j * 8, asz);
    CPA16(bD0, bSrc, 16);
    CPA16(bD0 + 16, bSrc + 8, 16);
    CP_COMMIT();

    for (int c = 0; c < 8; c++) {
        const int buf = c & 1;
        if (c < 7) {
            const __half* as = aSrc + (c + 1) * 32;
            const __half* bs = bSrc + (c + 1) * 32;
            uint32_t ad = buf ? aD0 : aD1;
            uint32_t bd = buf ? bD0 : bD1;
#pragma unroll
            for (int j = 0; j < 4; j++) CPA16(ad + j * 16, as + j * 8, asz);
            CPA16(bd, bs, 16);
            CPA16(bd + 16, bs + 8, 16);
        }
        CP_COMMIT();
        CP_WAIT1();
        __syncthreads();

        const uint32_t aB = aL0 + buf * 10240;
        const uint32_t bB = bL0 + buf * 5120;
#pragma unroll
        for (int s = 0; s < 2; s++) {
            uint32_t afr[2][4], bfr[8][2];
#pragma unroll
            for (int mi = 0; mi < 2; mi++)
                LDSM_X4(afr[mi][0], afr[mi][1], afr[mi][2], afr[mi][3],
                        aB + mi * (16 * 80) + s * 32);
#pragma unroll
            for (int p = 0; p < 4; p++)
                LDSM_X4(bfr[2 * p][0], bfr[2 * p][1], bfr[2 * p + 1][0], bfr[2 * p + 1][1],
                        bB + p * (16 * 80) + s * 32);
#pragma unroll
            for (int mi = 0; mi < 2; mi++)
#pragma unroll
                for (int ni = 0; ni < 8; ni++)
                    mma_f16(acc[mi][ni], afr[mi], bfr[ni]);
        }
        __syncthreads();
    }

#pragma unroll
    for (int mi = 0; mi < 2; mi++) {
        const int r0 = blockRow + warpRow + mi * 16 + g;
        const int r1 = r0 + 8;
        const bool v0 = r0 < M, v1 = r1 < M;
        float elA = 0.f, erA = 0.f, elB = 0.f, erB = 0.f;
#pragma unroll
        for (int ni = 0; ni < 8; ni++) {
            const int col = ni * 8 + 2 * t;
            float c0 = acc[mi][ni][0], c1 = acc[mi][ni][1];
            float c2 = acc[mi][ni][2], c3 = acc[mi][ni][3];
            float a0 = al[col], a1 = al[col + 1];
            float q0 = ar[col], q1 = ar[col + 1];
            elA += c0 * a0 + c1 * a1;  erA += c0 * q0 + c1 * q1;
            elB += c2 * a0 + c3 * a1;  erB += c2 * q0 + c3 * q1;
            if (v0) *(uint32_t*)&g_feat2h[(size_t)r0 * OUT_DIM + col] = h2_bits(__floats2half2_rn(c0, c1));
            if (v1) *(uint32_t*)&g_feat2h[(size_t)r1 * OUT_DIM + col] = h2_bits(__floats2half2_rn(c2, c3));
        }
#pragma unroll
        for (int o = 1; o <= 2; o <<= 1) {
            elA += __shfl_xor_sync(0xffffffffu, elA, o);
            erA += __shfl_xor_sync(0xffffffffu, erA, o);
            elB += __shfl_xor_sync(0xffffffffu, elB, o);
            erB += __shfl_xor_sync(0xffffffffu, erB, o);
        }
        if (t == 0) {
            if (v0) { g_el2[r0] = elA; g_er2[r0] = erA; }
            if (v1) { g_el2[r1] = elB; g_er2[r1] = erB; }
        }
    }
}

// ---------------- CSR build ----------------
__global__ void zero_cnt_kernel() {
    int i = blockIdx.x * blockDim.x + threadIdx.x;
    if (i < NNODES) g_cnt[i] = 0;
}

__global__ void hist_kernel(const int* __restrict__ dst) {
    int e = blockIdx.x * blockDim.x + threadIdx.x;
    if (e < NEDGES) atomicAdd(&g_cnt[dst[e]], 1);
}

__global__ void scan_kernel() {
    __shared__ int warpsum[32];
    int tid = threadIdx.x, lane = tid & 31, wid = tid >> 5;
    int carry = 0;
    for (int base = 0; base < NNODES; base += 4096) {
        int idx = base + tid * 4;
        int v0 = 0, v1 = 0, v2 = 0, v3 = 0;
        if (idx + 3 < NNODES) {
            int4 t = *(const int4*)&g_cnt[idx];
            v0 = t.x; v1 = t.y; v2 = t.z; v3 = t.w;
        } else {
            if (idx + 0 < NNODES) v0 = g_cnt[idx + 0];
            if (idx + 1 < NNODES) v1 = g_cnt[idx + 1];
            if (idx + 2 < NNODES) v2 = g_cnt[idx + 2];
            if (idx + 3 < NNODES) v3 = g_cnt[idx + 3];
        }
        int tsum = v0 + v1 + v2 + v3;
        int x = tsum;
#pragma unroll
        for (int o = 1; o < 32; o <<= 1) {
            int t = __shfl_up_sync(0xffffffffu, x, o);
            if (lane >= o) x += t;
        }
        if (lane == 31) warpsum[wid] = x;
        __syncthreads();
        if (wid == 0) {
            int w = warpsum[lane];
#pragma unroll
            for (int o = 1; o < 32; o <<= 1) {
                int t = __shfl_up_sync(0xffffffffu, w, o);
                if (lane >= o) w += t;
            }
            warpsum[lane] = w;
        }
        __syncthreads();
        int wexcl = (wid == 0) ? 0 : warpsum[wid - 1];
        int total = warpsum[31];
        int p = carry + wexcl + x - tsum;
        if (idx + 0 < NNODES) { g_off[idx + 0] = p;                g_cur[idx + 0] = p; }
        if (idx + 1 < NNODES) { g_off[idx + 1] = p + v0;           g_cur[idx + 1] = p + v0; }
        if (idx + 2 < NNODES) { g_off[idx + 2] = p + v0 + v1;      g_cur[idx + 2] = p + v0 + v1; }
        if (idx + 3 < NNODES) { g_off[idx + 3] = p + v0 + v1 + v2; g_cur[idx + 3] = p + v0 + v1 + v2; }
        carry += total;
        __syncthreads();
    }
    if (tid == 0) g_off[NNODES] = carry;
}

__global__ void scatter_kernel(const int* __restrict__ src, const int* __restrict__ dst) {
    int e = blockIdx.x * blockDim.x + threadIdx.x;
    if (e < NEDGES) {
        int p = atomicAdd(&g_cur[dst[e]], 1);
        g_csr_src[p] = src[e];
    }
}

// ---------------- layer 1 aggregation: warp per dst node; 2x unrolled; writes fp16 h1 ----------------
__global__ void agg1_kernel(const float* __restrict__ b1) {
    int n = (blockIdx.x * blockDim.x + threadIdx.x) >> 5;
    if (n >= NNODES) return;
    int lane = threadIdx.x & 31;
    int hh = lane >> 2;
    int db = (lane & 3) * 8;

    float ern = g_er1[n * H1 + hh];
    float wsum = 0.f;
    float a[8];
#pragma unroll
    for (int k = 0; k < 8; k++) a[k] = 0.f;

    int beg = g_off[n], end = g_off[n + 1];
    int e = beg;
    for (; e + 2 <= end; e += 2) {
        int s0 = g_csr_src[e], s1 = g_csr_src[e + 1];
        float x0 = g_el1[s0 * H1 + hh] + ern;
        float x1 = g_el1[s1 * H1 + hh] + ern;
        uint4 hv0 = *(const uint4*)(g_feat1h + (size_t)s0 * HD1 + hh * HID + db);
        uint4 hv1 = *(const uint4*)(g_feat1h + (size_t)s1 * HD1 + hh * HID + db);
        x0 = fmaxf(x0, 0.2f * x0);
        x1 = fmaxf(x1, 0.2f * x1);
        float w0 = __expf(x0), w1 = __expf(x1);
        wsum += w0 + w1;
        const __half2* hp0 = (const __half2*)&hv0;
        const __half2* hp1 = (const __half2*)&hv1;
#pragma unroll
        for (int j = 0; j < 4; j++) {
            float2 f0 = __half22float2(hp0[j]);
            float2 f1 = __half22float2(hp1[j]);
            a[2 * j + 0] += w0 * f0.x + w1 * f1.x;
            a[2 * j + 1] += w0 * f0.y + w1 * f1.y;
        }
    }
    if (e < end) {
        int s = g_csr_src[e];
        float x = g_el1[s * H1 + hh] + ern;
        x = fmaxf(x, 0.2f * x);
        float w = __expf(x);
        wsum += w;
        uint4 hv = *(const uint4*)(g_feat1h + (size_t)s * HD1 + hh * HID + db);
        const __half2* hp = (const __half2*)&hv;
#pragma unroll
        for (int j = 0; j < 4; j++) {
            float2 f = __half22float2(hp[j]);
            a[2 * j + 0] += w * f.x;
            a[2 * j + 1] += w * f.y;
        }
    }

    float inv = 1.f / wsum;
    const float* bp = b1 + hh * HID + db;
#pragma unroll
    for (int k = 0; k < 8; k++) {
        float v = a[k] * inv + bp[k];
        a[k] = v > 0.f ? v : (__expf(v) - 1.f);   // ELU
    }
    uint4 w = make_uint4(h2_bits(__floats2half2_rn(a[0], a[1])),
                         h2_bits(__floats2half2_rn(a[2], a[3])),
                         h2_bits(__floats2half2_rn(a[4], a[5])),
                         h2_bits(__floats2half2_rn(a[6], a[7])));
    *(uint4*)&g_h1h[(size_t)n * HD1 + hh * HID + db] = w;
}

// ---------------- layer 2 aggregation (fp16 feats, 2x unrolled) ----------------
__global__ void agg2_kernel(const float* __restrict__ b2, float* __restrict__ out) {
    int n = (blockIdx.x * blockDim.x + threadIdx.x) >> 5;
    if (n >= NNODES) return;
    int lane = threadIdx.x & 31;

    float ern = g_er2[n];
    float wsum = 0.f;
    float a0 = 0.f, a1 = 0.f;

    int beg = g_off[n], end = g_off[n + 1];
    int e = beg;
    for (; e + 2 <= end; e += 2) {
        int s0 = g_csr_src[e], s1 = g_csr_src[e + 1];
        float x0 = g_el2[s0] + ern;
        float x1 = g_el2[s1] + ern;
        __half2 hv0 = *(const __half2*)(g_feat2h + (size_t)s0 * OUT_DIM + lane * 2);
        __half2 hv1 = *(const __half2*)(g_feat2h + (size_t)s1 * OUT_DIM + lane * 2);
        x0 = fmaxf(x0, 0.2f * x0);
        x1 = fmaxf(x1, 0.2f * x1);
        float w0 = __expf(x0), w1 = __expf(x1);
        wsum += w0 + w1;
        float2 f0 = __half22float2(hv0);
        float2 f1 = __half22float2(hv1);
        a0 += w0 * f0.x + w1 * f1.x;
        a1 += w0 * f0.y + w1 * f1.y;
    }
    if (e < end) {
        int s = g_csr_src[e];
        float x = g_el2[s] + ern;
        x = fmaxf(x, 0.2f * x);
        float w = __expf(x);
        wsum += w;
        float2 f = __half22float2(*(const __half2*)(g_feat2h + (size_t)s * OUT_DIM + lane * 2));
        a0 += w * f.x;
        a1 += w * f.y;
    }

    float inv = 1.f / wsum;
    out[(size_t)n * OUT_DIM + lane * 2 + 0] = a0 * inv + b2[lane * 2 + 0];
    out[(size_t)n * OUT_DIM + lane * 2 + 1] = a1 * inv + b2[lane * 2 + 1];
}

// ---------------- launch ----------------
extern "C" void kernel_launch(void* const* d_in, const int* in_sizes, int n_in,
                              void* d_out, int out_size) {
    const float* h   = (const float*)d_in[0];
    const float* W1  = (const float*)d_in[1];
    const float* al1 = (const float*)d_in[2];
    const float* ar1 = (const float*)d_in[3];
    const float* b1  = (const float*)d_in[4];
    const float* W2  = (const float*)d_in[5];
    const float* al2 = (const float*)d_in[6];
    const float* ar2 = (const float*)d_in[7];
    const float* b2  = (const float*)d_in[8];
    const int*   src = (const int*)d_in[9];
    const int*   dst = (const int*)d_in[10];
    float* out = (float*)d_out;

    static cudaStream_t s_csr = nullptr;
    static cudaEvent_t ev_fork = nullptr, ev_join = nullptr;
    if (s_csr == nullptr) {
        cudaStreamCreateWithFlags(&s_csr, cudaStreamNonBlocking);
        cudaEventCreateWithFlags(&ev_fork, cudaEventDisableTiming);
        cudaEventCreateWithFlags(&ev_join, cudaEventDisableTiming);
    }

    const int nwarpblocks = (NNODES * 32 + 255) / 256;
    const int eblocks = (NEDGES + 255) / 256;
    const int gblocks = (NNODES + 127) / 128;

    cudaEventRecord(ev_fork, 0);
    cudaStreamWaitEvent(s_csr, ev_fork, 0);
    zero_cnt_kernel<<<(NNODES + 255) / 256, 256, 0, s_csr>>>();          // 1
    hist_kernel<<<eblocks, 256, 0, s_csr>>>(dst);                        // 2
    prep_kernel<<<HBLOCKS + 256 + 64, 256>>>(h, W1, W2);                 // 3 (main)
    hgemm1_kernel<<<dim3(4, gblocks), 256>>>(NNODES, al1, ar1);          // 4 (main)
    scan_kernel<<<1, 1024, 0, s_csr>>>();                                // 5
    scatter_kernel<<<eblocks, 256, 0, s_csr>>>(src, dst);                // 6
    cudaEventRecord(ev_join, s_csr);

    cudaStreamWaitEvent(0, ev_join, 0);
    agg1_kernel<<<nwarpblocks, 256>>>(b1);                               // 7
    hgemm2_kernel<<<gblocks, 128>>>(NNODES, al2, ar2);                   // 8
    agg2_kernel<<<nwarpblocks, 256>>>(b2, out);                          // 9
}

// round 13
// speedup vs baseline: 2.3256x; 1.0822x over previous
#include <cuda_runtime.h>
#include <cuda_fp16.h>
#include <cstdint>

#define NNODES 50000
#define NEDGES 850000
#define IN_DIM 256
#define HID 32
#define H1 8
#define OUT_DIM 64
#define HD1 (H1*HID)   // 256
#define KDIM 256

// ---------------- scratch ----------------
__device__ __align__(16) __half g_W1t[HD1 * KDIM];
__device__ __align__(16) __half g_W2t[OUT_DIM * KDIM];
__device__ __align__(16) __half g_feat1h[NNODES * HD1];
__device__ __align__(16) __half g_h1h[NNODES * HD1];
__device__ __align__(16) __half g_feat2h[NNODES * OUT_DIM];
__device__ __align__(16) float  g_el1[NNODES * H1];
__device__ __align__(16) float  g_er1[NNODES * H1];
__device__ __align__(16) float  g_el2[NNODES];
__device__ __align__(16) float  g_er2[NNODES];
__device__ __align__(16) int    g_cnt[NNODES];
__device__ __align__(16) int    g_off[NNODES + 1];
__device__ __align__(16) int    g_cur[NNODES];
__device__ __align__(16) int    g_csr_src[NEDGES];

#define CPA16(dst, src, sz) \
    asm volatile("cp.async.cg.shared.global [%0], [%1], 16, %2;" :: "r"(dst), "l"(src), "r"(sz) : "memory")
#define CP_COMMIT() asm volatile("cp.async.commit_group;" ::: "memory")
#define CP_WAIT1()  asm volatile("cp.async.wait_group 1;" ::: "memory")

#define LDSM_X4(r0, r1, r2, r3, addr) \
    asm volatile("ldmatrix.sync.aligned.m8n8.x4.shared.b16 {%0,%1,%2,%3}, [%4];" \
        : "=r"(r0), "=r"(r1), "=r"(r2), "=r"(r3) : "r"(addr))

__device__ __forceinline__ uint32_t smem_u32(const void* p) {
    uint32_t a;
    asm("{ .reg .u64 t; cvta.to.shared.u64 t, %1; cvt.u32.u64 %0, t; }" : "=r"(a) : "l"(p));
    return a;
}
__device__ __forceinline__ uint32_t h2_bits(__half2 h) {
    uint32_t u;
    memcpy(&u, &h, 4);
    return u;
}

__device__ __forceinline__ void mma_f16(float c[4], const uint32_t a[4], const uint32_t b[2]) {
    asm("mma.sync.aligned.m16n8k16.row.col.f32.f16.f16.f32 "
        "{%0,%1,%2,%3}, {%4,%5,%6,%7}, {%8,%9}, {%0,%1,%2,%3};"
        : "+f"(c[0]), "+f"(c[1]), "+f"(c[2]), "+f"(c[3])
        : "r"(a[0]), "r"(a[1]), "r"(a[2]), "r"(a[3]), "r"(b[0]), "r"(b[1]));
}

// ---------------- prep: weight transposes only ----------------
__global__ void prepw_kernel(const float* __restrict__ W1, const float* __restrict__ W2) {
    int b = blockIdx.x;
    if (b < 256) {
        int i = b * 256 + threadIdx.x;          // 0..65535
        int n = i >> 8, k = i & 255;
        g_W1t[i] = __float2half(W1[k * HD1 + n]);
    } else {
        int i = (b - 256) * 256 + threadIdx.x;  // 0..16383
        int n = i >> 8, k = i & 255;
        g_W2t[i] = __float2half(W2[k * OUT_DIM + n]);
    }
}

// ---------------- GEMM1: fp16 mma + ldmatrix; A converted fp32->fp16 in-kernel ----------------
// Block 128 rows x 128 cols; 8 warps (4m x 2n); warp tile 32x64. Smem stride 40 halves (80B).
__global__ __launch_bounds__(256) void hgemm1_kernel(
    const float* __restrict__ A, int M, const float* __restrict__ al, const float* __restrict__ ar)
{
    __shared__ __align__(16) __half Asm[2][128 * 40];   // 10240 B per buf
    __shared__ __align__(16) __half Bsm[2][128 * 40];   // 10240 B per buf

    const int tid = threadIdx.x;
    const int lane = tid & 31;
    const int warp = tid >> 5;
    const int g = lane >> 2;
    const int t = lane & 3;
    const int warpRow = (warp & 3) * 32;
    const int warpCol = (warp >> 2) * 64;
    const int blockRow = blockIdx.y * 128;
    const int colbase = blockIdx.x * 128;

    // A staging: 2 threads/row, 16 fp32 each -> cvt -> 16 halves
    const int arow = tid >> 1;
    const int kh = (tid & 1) * 16;              // halves
    const int agr = blockRow + arow;
    const bool aval = agr < M;
    const float* aSrc = A + (size_t)agr * KDIM + kh;
    __half* aDst0 = &Asm[0][arow * 40 + kh];

    // B staging: 2 threads/col, 16 halves each via 2 cp.async
    const int bcol = tid >> 1;
    const int bseg = (tid & 1) * 16;            // halves
    const __half* bSrc = g_W1t + (size_t)(colbase + bcol) * KDIM + bseg;
    const uint32_t bD0 = smem_u32(&Bsm[0][bcol * 40 + bseg]);
    const uint32_t bD1 = smem_u32(&Bsm[1][bcol * 40 + bseg]);

    // ldmatrix addresses
    const uint32_t aL0 = smem_u32(&Asm[0][0]) + (warpRow + (lane & 15)) * 80 + (lane >> 4) * 16;
    const uint32_t bL0 = smem_u32(&Bsm[0][0]) + (warpCol + (lane & 7) + ((lane >> 4) << 3)) * 80 + (((lane >> 3) & 1) * 16);

    float acc[2][8][4];
#pragma unroll
    for (int mi = 0; mi < 2; mi++)
#pragma unroll
        for (int ni = 0; ni < 8; ni++)
#pragma unroll
            for (int k = 0; k < 4; k++) acc[mi][ni][k] = 0.f;

    float4 av[4];
    auto ldgA = [&](int c) {
#pragma unroll
        for (int q = 0; q < 4; q++)
            av[q] = aval ? *(const float4*)(aSrc + c * 32 + q * 4)
                         : make_float4(0.f, 0.f, 0.f, 0.f);
    };
    auto stsA = [&](int buf) {
        __half* d = aDst0 + buf * (128 * 40);
        uint4 w0, w1;
        w0.x = h2_bits(__floats2half2_rn(av[0].x, av[0].y));
        w0.y = h2_bits(__floats2half2_rn(av[0].z, av[0].w));
        w0.z = h2_bits(__floats2half2_rn(av[1].x, av[1].y));
        w0.w = h2_bits(__floats2half2_rn(av[1].z, av[1].w));
        w1.x = h2_bits(__floats2half2_rn(av[2].x, av[2].y));
        w1.y = h2_bits(__floats2half2_rn(av[2].z, av[2].w));
        w1.z = h2_bits(__floats2half2_rn(av[3].x, av[3].y));
        w1.w = h2_bits(__floats2half2_rn(av[3].z, av[3].w));
        *(uint4*)d = w0;
        *(uint4*)(d + 8) = w1;
    };
    auto cpB = [&](int c, int buf) {
        const __half* s = bSrc + c * 32;
        uint32_t d = buf ? bD1 : bD0;
        CPA16(d, s, 16);
        CPA16(d + 16, s + 8, 16);
    };

    // prologue
    ldgA(0); stsA(0);
    cpB(0, 0); CP_COMMIT();
    ldgA(1);

    for (int c = 0; c < 8; c++) {
        const int buf = c & 1;
        if (c < 7) cpB(c + 1, buf ^ 1);
        CP_COMMIT();
        CP_WAIT1();
        __syncthreads();

        const uint32_t aB = aL0 + buf * 10240;
        const uint32_t bB = bL0 + buf * 10240;
#pragma unroll
        for (int s = 0; s < 2; s++) {
            uint32_t afr[2][4], bfr[8][2];
#pragma unroll
            for (int mi = 0; mi < 2; mi++)
                LDSM_X4(afr[mi][0], afr[mi][1], afr[mi][2], afr[mi][3],
                        aB + mi * (16 * 80) + s * 32);
#pragma unroll
            for (int p = 0; p < 4; p++)
                LDSM_X4(bfr[2 * p][0], bfr[2 * p][1], bfr[2 * p + 1][0], bfr[2 * p + 1][1],
                        bB + p * (16 * 80) + s * 32);
#pragma unroll
            for (int mi = 0; mi < 2; mi++)
#pragma unroll
                for (int ni = 0; ni < 8; ni++)
                    mma_f16(acc[mi][ni], afr[mi], bfr[ni]);
        }
        if (c < 7) {
            stsA(buf ^ 1);                  // chunk c+1 -> other buffer (A region disjoint from compute's buf)
            if (c < 6) ldgA(c + 2);
        }
        __syncthreads();
    }

    // ---- epilogue: fp16 feat1 + fused el1/er1 (warp covers 2 heads) ----
    const int head0 = (colbase + warpCol) >> 5;
#pragma unroll
    for (int mi = 0; mi < 2; mi++) {
        const int r0 = blockRow + warpRow + mi * 16 + g;
        const int r1 = r0 + 8;
        const bool v0 = r0 < M, v1 = r1 < M;
        float elL[2] = {0.f, 0.f}, erL[2] = {0.f, 0.f};
        float elH[2] = {0.f, 0.f}, erH[2] = {0.f, 0.f};
#pragma unroll
        for (int ni = 0; ni < 8; ni++) {
            const int hsel = ni >> 2;
            const int col = colbase + warpCol + ni * 8 + 2 * t;
            float c0 = acc[mi][ni][0], c1 = acc[mi][ni][1];
            float c2 = acc[mi][ni][2], c3 = acc[mi][ni][3];
            float a0 = al[col], a1 = al[col + 1];
            float q0 = ar[col], q1 = ar[col + 1];
            elL[hsel] += c0 * a0 + c1 * a1;  erL[hsel] += c0 * q0 + c1 * q1;
            elH[hsel] += c2 * a0 + c3 * a1;  erH[hsel] += c2 * q0 + c3 * q1;
            if (v0) *(uint32_t*)&g_feat1h[(size_t)r0 * HD1 + col] = h2_bits(__floats2half2_rn(c0, c1));
            if (v1) *(uint32_t*)&g_feat1h[(size_t)r1 * HD1 + col] = h2_bits(__floats2half2_rn(c2, c3));
        }
#pragma unroll
        for (int hsel = 0; hsel < 2; hsel++) {
#pragma unroll
            for (int o = 1; o <= 2; o <<= 1) {
                elL[hsel] += __shfl_xor_sync(0xffffffffu, elL[hsel], o);
                erL[hsel] += __shfl_xor_sync(0xffffffffu, erL[hsel], o);
                elH[hsel] += __shfl_xor_sync(0xffffffffu, elH[hsel], o);
                erH[hsel] += __shfl_xor_sync(0xffffffffu, erH[hsel], o);
            }
        }
        if (t == 0) {
#pragma unroll
            for (int hsel = 0; hsel < 2; hsel++) {
                int head = head0 + hsel;
                if (v0) { g_el1[r0 * H1 + head] = elL[hsel]; g_er1[r0 * H1 + head] = erL[hsel]; }
                if (v1) { g_el1[r1 * H1 + head] = elH[hsel]; g_er1[r1 * H1 + head] = erH[hsel]; }
            }
        }
    }
}

// ---------------- GEMM2: fp16 mma + ldmatrix, 4 warps, warp tile 32x64 ----------------
__global__ __launch_bounds__(128) void hgemm2_kernel(
    int M, const float* __restrict__ al, const float* __restrict__ ar)
{
    __shared__ __align__(16) __half Asm[2][128 * 40];
    __shared__ __align__(16) __half Bsm[2][64 * 40];

    const int tid = threadIdx.x;
    const int lane = tid & 31;
    const int warp = tid >> 5;
    const int g = lane >> 2;
    const int t = lane & 3;
    const int warpRow = warp * 32;
    const int blockRow = blockIdx.x * 128;

    const int arow = tid;
    const int agr = blockRow + arow;
    const int asz = (agr < M) ? 16 : 0;
    const __half* aSrc = g_h1h + (size_t)agr * KDIM;
    const int bcol = tid >> 1;
    const int bseg = (tid & 1) * 16;
    const __half* bSrc = g_W2t + (size_t)bcol * KDIM + bseg;
    const uint32_t aD0 = smem_u32(&Asm[0][arow * 40]);
    const uint32_t aD1 = smem_u32(&Asm[1][arow * 40]);
    const uint32_t bD0 = smem_u32(&Bsm[0][bcol * 40 + bseg]);
    const uint32_t bD1 = smem_u32(&Bsm[1][bcol * 40 + bseg]);

    const uint32_t aL0 = smem_u32(&Asm[0][0]) + (warpRow + (lane & 15)) * 80 + (lane >> 4) * 16;
    const uint32_t bL0 = smem_u32(&Bsm[0][0]) + ((lane & 7) + ((lane >> 4) << 3)) * 80 + (((lane >> 3) & 1) * 16);

    float acc[2][8][4];
#pragma unroll
    for (int mi = 0; mi < 2; mi++)
#pragma unroll
        for (int ni = 0; ni < 8; ni++)
#pragma unroll
            for (int k = 0; k < 4; k++) acc[mi][ni][k] = 0.f;

#pragma unroll
    for (int j = 0; j < 4; j++) CPA16(aD0 + j * 16, aSrc + j * 8, asz);
    CPA16(bD0, bSrc, 16);
    CPA16(bD0 + 16, bSrc + 8, 16);
    CP_COMMIT();

    for (int c = 0; c < 8; c++) {
        const int buf = c & 1;
        if (c < 7) {
            const __half* as = aSrc + (c + 1) * 32;
            const __half* bs = bSrc + (c + 1) * 32;
            uint32_t ad = buf ? aD0 : aD1;
            uint32_t bd = buf ? bD0 : bD1;
#pragma unroll
            for (int j = 0; j < 4; j++) CPA16(ad + j * 16, as + j * 8, asz);
            CPA16(bd, bs, 16);
            CPA16(bd + 16, bs + 8, 16);
        }
        CP_COMMIT();
        CP_WAIT1();
        __syncthreads();

        const uint32_t aB = aL0 + buf * 10240;
        const uint32_t bB = bL0 + buf * 5120;
#pragma unroll
        for (int s = 0; s < 2; s++) {
            uint32_t afr[2][4], bfr[8][2];
#pragma unroll
            for (int mi = 0; mi < 2; mi++)
                LDSM_X4(afr[mi][0], afr[mi][1], afr[mi][2], afr[mi][3],
                        aB + mi * (16 * 80) + s * 32);
#pragma unroll
            for (int p = 0; p < 4; p++)
                LDSM_X4(bfr[2 * p][0], bfr[2 * p][1], bfr[2 * p + 1][0], bfr[2 * p + 1][1],
                        bB + p * (16 * 80) + s * 32);
#pragma unroll
            for (int mi = 0; mi < 2; mi++)
#pragma unroll
                for (int ni = 0; ni < 8; ni++)
                    mma_f16(acc[mi][ni], afr[mi], bfr[ni]);
        }
        __syncthreads();
    }

#pragma unroll
    for (int mi = 0; mi < 2; mi++) {
        const int r0 = blockRow + warpRow + mi * 16 + g;
        const int r1 = r0 + 8;
        const bool v0 = r0 < M, v1 = r1 < M;
        float elA = 0.f, erA = 0.f, elB = 0.f, erB = 0.f;
#pragma unroll
        for (int ni = 0; ni < 8; ni++) {
            const int col = ni * 8 + 2 * t;
            float c0 = acc[mi][ni][0], c1 = acc[mi][ni][1];
            float c2 = acc[mi][ni][2], c3 = acc[mi][ni][3];
            float a0 = al[col], a1 = al[col + 1];
            float q0 = ar[col], q1 = ar[col + 1];
            elA += c0 * a0 + c1 * a1;  erA += c0 * q0 + c1 * q1;
            elB += c2 * a0 + c3 * a1;  erB += c2 * q0 + c3 * q1;
            if (v0) *(uint32_t*)&g_feat2h[(size_t)r0 * OUT_DIM + col] = h2_bits(__floats2half2_rn(c0, c1));
            if (v1) *(uint32_t*)&g_feat2h[(size_t)r1 * OUT_DIM + col] = h2_bits(__floats2half2_rn(c2, c3));
        }
#pragma unroll
        for (int o = 1; o <= 2; o <<= 1) {
            elA += __shfl_xor_sync(0xffffffffu, elA, o);
            erA += __shfl_xor_sync(0xffffffffu, erA, o);
            elB += __shfl_xor_sync(0xffffffffu, elB, o);
            erB += __shfl_xor_sync(0xffffffffu, erB, o);
        }
        if (t == 0) {
            if (v0) { g_el2[r0] = elA; g_er2[r0] = erA; }
            if (v1) { g_el2[r1] = elB; g_er2[r1] = erB; }
        }
    }
}

// ---------------- CSR build ----------------
__global__ void zero_cnt_kernel() {
    int i = blockIdx.x * blockDim.x + threadIdx.x;
    if (i < NNODES) g_cnt[i] = 0;
}

__global__ void hist_kernel(const int* __restrict__ dst) {
    int e = blockIdx.x * blockDim.x + threadIdx.x;
    if (e < NEDGES) atomicAdd(&g_cnt[dst[e]], 1);
}

__global__ void scan_kernel() {
    __shared__ int warpsum[32];
    int tid = threadIdx.x, lane = tid & 31, wid = tid >> 5;
    int carry = 0;
    for (int base = 0; base < NNODES; base += 4096) {
        int idx = base + tid * 4;
        int v0 = 0, v1 = 0, v2 = 0, v3 = 0;
        if (idx + 3 < NNODES) {
            int4 t = *(const int4*)&g_cnt[idx];
            v0 = t.x; v1 = t.y; v2 = t.z; v3 = t.w;
        } else {
            if (idx + 0 < NNODES) v0 = g_cnt[idx + 0];
            if (idx + 1 < NNODES) v1 = g_cnt[idx + 1];
            if (idx + 2 < NNODES) v2 = g_cnt[idx + 2];
            if (idx + 3 < NNODES) v3 = g_cnt[idx + 3];
        }
        int tsum = v0 + v1 + v2 + v3;
        int x = tsum;
#pragma unroll
        for (int o = 1; o < 32; o <<= 1) {
            int t = __shfl_up_sync(0xffffffffu, x, o);
            if (lane >= o) x += t;
        }
        if (lane == 31) warpsum[wid] = x;
        __syncthreads();
        if (wid == 0) {
            int w = warpsum[lane];
#pragma unroll
            for (int o = 1; o < 32; o <<= 1) {
                int t = __shfl_up_sync(0xffffffffu, w, o);
                if (lane >= o) w += t;
            }
            warpsum[lane] = w;
        }
        __syncthreads();
        int wexcl = (wid == 0) ? 0 : warpsum[wid - 1];
        int total = warpsum[31];
        int p = carry + wexcl + x - tsum;
        if (idx + 0 < NNODES) { g_off[idx + 0] = p;                g_cur[idx + 0] = p; }
        if (idx + 1 < NNODES) { g_off[idx + 1] = p + v0;           g_cur[idx + 1] = p + v0; }
        if (idx + 2 < NNODES) { g_off[idx + 2] = p + v0 + v1;      g_cur[idx + 2] = p + v0 + v1; }
        if (idx + 3 < NNODES) { g_off[idx + 3] = p + v0 + v1 + v2; g_cur[idx + 3] = p + v0 + v1 + v2; }
        carry += total;
        __syncthreads();
    }
    if (tid == 0) g_off[NNODES] = carry;
}

__global__ void scatter_kernel(const int* __restrict__ src, const int* __restrict__ dst) {
    int e = blockIdx.x * blockDim.x + threadIdx.x;
    if (e < NEDGES) {
        int p = atomicAdd(&g_cur[dst[e]], 1);
        g_csr_src[p] = src[e];
    }
}

// ---------------- layer 1 aggregation (2x unrolled, fp16 feats, fp16 h1 out) ----------------
__global__ void agg1_kernel(const float* __restrict__ b1) {
    int n = (blockIdx.x * blockDim.x + threadIdx.x) >> 5;
    if (n >= NNODES) return;
    int lane = threadIdx.x & 31;
    int hh = lane >> 2;
    int db = (lane & 3) * 8;

    float ern = g_er1[n * H1 + hh];
    float wsum = 0.f;
    float a[8];
#pragma unroll
    for (int k = 0; k < 8; k++) a[k] = 0.f;

    int beg = g_off[n], end = g_off[n + 1];
    int e = beg;
    for (; e + 2 <= end; e += 2) {
        int s0 = g_csr_src[e], s1 = g_csr_src[e + 1];
        float x0 = g_el1[s0 * H1 + hh] + ern;
        float x1 = g_el1[s1 * H1 + hh] + ern;
        uint4 hv0 = *(const uint4*)(g_feat1h + (size_t)s0 * HD1 + hh * HID + db);
        uint4 hv1 = *(const uint4*)(g_feat1h + (size_t)s1 * HD1 + hh * HID + db);
        x0 = fmaxf(x0, 0.2f * x0);
        x1 = fmaxf(x1, 0.2f * x1);
        float w0 = __expf(x0), w1 = __expf(x1);
        wsum += w0 + w1;
        const __half2* hp0 = (const __half2*)&hv0;
        const __half2* hp1 = (const __half2*)&hv1;
#pragma unroll
        for (int j = 0; j < 4; j++) {
            float2 f0 = __half22float2(hp0[j]);
            float2 f1 = __half22float2(hp1[j]);
            a[2 * j + 0] += w0 * f0.x + w1 * f1.x;
            a[2 * j + 1] += w0 * f0.y + w1 * f1.y;
        }
    }
    if (e < end) {
        int s = g_csr_src[e];
        float x = g_el1[s * H1 + hh] + ern;
        x = fmaxf(x, 0.2f * x);
        float w = __expf(x);
        wsum += w;
        uint4 hv = *(const uint4*)(g_feat1h + (size_t)s * HD1 + hh * HID + db);
        const __half2* hp = (const __half2*)&hv;
#pragma unroll
        for (int j = 0; j < 4; j++) {
            float2 f = __half22float2(hp[j]);
            a[2 * j + 0] += w * f.x;
            a[2 * j + 1] += w * f.y;
        }
    }

    float inv = 1.f / wsum;
    const float* bp = b1 + hh * HID + db;
#pragma unroll
    for (int k = 0; k < 8; k++) {
        float v = a[k] * inv + bp[k];
        a[k] = v > 0.f ? v : (__expf(v) - 1.f);   // ELU
    }
    uint4 w = make_uint4(h2_bits(__floats2half2_rn(a[0], a[1])),
                         h2_bits(__floats2half2_rn(a[2], a[3])),
                         h2_bits(__floats2half2_rn(a[4], a[5])),
                         h2_bits(__floats2half2_rn(a[6], a[7])));
    *(uint4*)&g_h1h[(size_t)n * HD1 + hh * HID + db] = w;
}

// ---------------- layer 2 aggregation (fp16 feats, 2x unrolled) ----------------
__global__ void agg2_kernel(const float* __restrict__ b2, float* __restrict__ out) {
    int n = (blockIdx.x * blockDim.x + threadIdx.x) >> 5;
    if (n >= NNODES) return;
    int lane = threadIdx.x & 31;

    float ern = g_er2[n];
    float wsum = 0.f;
    float a0 = 0.f, a1 = 0.f;

    int beg = g_off[n], end = g_off[n + 1];
    int e = beg;
    for (; e + 2 <= end; e += 2) {
        int s0 = g_csr_src[e], s1 = g_csr_src[e + 1];
        float x0 = g_el2[s0] + ern;
        float x1 = g_el2[s1] + ern;
        __half2 hv0 = *(const __half2*)(g_feat2h + (size_t)s0 * OUT_DIM + lane * 2);
        __half2 hv1 = *(const __half2*)(g_feat2h + (size_t)s1 * OUT_DIM + lane * 2);
        x0 = fmaxf(x0, 0.2f * x0);
        x1 = fmaxf(x1, 0.2f * x1);
        float w0 = __expf(x0), w1 = __expf(x1);
        wsum += w0 + w1;
        float2 f0 = __half22float2(hv0);
        float2 f1 = __half22float2(hv1);
        a0 += w0 * f0.x + w1 * f1.x;
        a1 += w0 * f0.y + w1 * f1.y;
    }
    if (e < end) {
        int s = g_csr_src[e];
        float x = g_el2[s] + ern;
        x = fmaxf(x, 0.2f * x);
        float w = __expf(x);
        wsum += w;
        float2 f = __half22float2(*(const __half2*)(g_feat2h + (size_t)s * OUT_DIM + lane * 2));
        a0 += w * f.x;
        a1 += w * f.y;
    }

    float inv = 1.f / wsum;
    out[(size_t)n * OUT_DIM + lane * 2 + 0] = a0 * inv + b2[lane * 2 + 0];
    out[(size_t)n * OUT_DIM + lane * 2 + 1] = a1 * inv + b2[lane * 2 + 1];
}

// ---------------- launch ----------------
extern "C" void kernel_launch(void* const* d_in, const int* in_sizes, int n_in,
                              void* d_out, int out_size) {
    const float* h   = (const float*)d_in[0];
    const float* W1  = (const float*)d_in[1];
    const float* al1 = (const float*)d_in[2];
    const float* ar1 = (const float*)d_in[3];
    const float* b1  = (const float*)d_in[4];
    const float* W2  = (const float*)d_in[5];
    const float* al2 = (const float*)d_in[6];
    const float* ar2 = (const float*)d_in[7];
    const float* b2  = (const float*)d_in[8];
    const int*   src = (const int*)d_in[9];
    const int*   dst = (const int*)d_in[10];
    float* out = (float*)d_out;

    static cudaStream_t s_csr = nullptr;
    static cudaEvent_t ev_fork = nullptr, ev_join = nullptr;
    if (s_csr == nullptr) {
        cudaStreamCreateWithFlags(&s_csr, cudaStreamNonBlocking);
        cudaEventCreateWithFlags(&ev_fork, cudaEventDisableTiming);
        cudaEventCreateWithFlags(&ev_join, cudaEventDisableTiming);
    }

    const int nwarpblocks = (NNODES * 32 + 255) / 256;
    const int eblocks = (NEDGES + 255) / 256;
    const int gblocks = (NNODES + 127) / 128;

    cudaEventRecord(ev_fork, 0);
    cudaStreamWaitEvent(s_csr, ev_fork, 0);
    zero_cnt_kernel<<<(NNODES + 255) / 256, 256, 0, s_csr>>>();          // 1
    hist_kernel<<<eblocks, 256, 0, s_csr>>>(dst);                        // 2
    prepw_kernel<<<320, 256>>>(W1, W2);                                  // 3 (main)
    hgemm1_kernel<<<dim3(2, gblocks), 256>>>(h, NNODES, al1, ar1);       // 4 (main, ncu window)
    scan_kernel<<<1, 1024, 0, s_csr>>>();                                // 5
    scatter_kernel<<<eblocks, 256, 0, s_csr>>>(src, dst);                // 6
    cudaEventRecord(ev_join, s_csr);

    cudaStreamWaitEvent(0, ev_join, 0);
    agg1_kernel<<<nwarpblocks, 256>>>(b1);                               // 7
    hgemm2_kernel<<<gblocks, 128>>>(NNODES, al2, ar2);                   // 8
    agg2_kernel<<<nwarpblocks, 256>>>(b2, out);                          // 9
}